// round 1
// baseline (speedup 1.0000x reference)
#include <cuda_runtime.h>
#include <cuda_bf16.h>
#include <math.h>

// ---------------- problem constants ----------------
#define Bq   4
#define Nn_  1024
#define DIM  512
#define Hh   8
#define DH   64
#define MLPD 2048
#define ROWS (Bq * Nn_)            // 4096 token rows
#define HB   (Hh * Bq)             // 32 attention batches
#define EPS  1e-5f

// ---------------- device scratch (no allocs allowed) ----------------
__device__ float g_xn [3 * ROWS * DIM];       // normalized q,k,v        24 MB
__device__ float g_f  [3 * ROWS * DIM];       // fq,fk,fv  [b,n,h*d]     24 MB
__device__ float g_S  [(size_t)HB * Nn_ * Nn_]; // scores                128 MB
__device__ float g_ao [ROWS * DIM];           // attention out            8 MB
__device__ float g_q2 [ROWS * DIM];           // residual 1               8 MB
__device__ float g_xn2[ROWS * DIM];           // LN2 output               8 MB
__device__ float g_u  [ROWS * MLPD];          // gelu hidden             32 MB
__device__ float g_qinv [HB * Nn_];
__device__ float g_qmean[HB * Nn_];
__device__ float g_qvar [HB * Nn_];
__device__ float g_kinv [HB * Nn_];
__device__ float g_kmean[HB * Nn_];
__device__ float g_kvar [HB * Nn_];
__device__ float g_hg [2 * Hh * DH];          // per-head global means (q,k)
__device__ float g_w3 [Hh * 3];               // mixing weights

// ---------------- layernorm over rows of 512 ----------------
__global__ void ln_kernel(const float* __restrict__ x, const float* __restrict__ g,
                          const float* __restrict__ bb, float* __restrict__ y)
{
    int row = blockIdx.x;
    int tid = threadIdx.x;                     // 256 threads, 2 elems each
    const float* xr = x + (size_t)row * DIM;
    float v0 = xr[tid], v1 = xr[tid + 256];
    float s = v0 + v1, ss = v0 * v0 + v1 * v1;
    __shared__ float rs[256], rss[256];
    rs[tid] = s; rss[tid] = ss;
    __syncthreads();
    for (int off = 128; off > 0; off >>= 1) {
        if (tid < off) { rs[tid] += rs[tid + off]; rss[tid] += rss[tid + off]; }
        __syncthreads();
    }
    float mean = rs[0] * (1.f / DIM);
    float var  = rss[0] * (1.f / DIM) - mean * mean;
    float inv  = rsqrtf(var + EPS);
    float* yr = y + (size_t)row * DIM;
    yr[tid]       = (v0 - mean) * inv * g[tid]       + bb[tid];
    yr[tid + 256] = (v1 - mean) * inv * g[tid + 256] + bb[tid + 256];
}

// ---------------- generic dense GEMM: C = A[M,K] @ W[N,K]^T ----------------
// MODE: 0 plain, 1 +bias, 2 +bias+gelu(exact), 3 +bias+residual
template <int MODE>
__global__ void gemm_kernel(const float* __restrict__ A, const float* __restrict__ W,
                            const float* __restrict__ bias, const float* __restrict__ res,
                            float* __restrict__ C, int M, int Nc, int K)
{
    __shared__ float As[64][17];
    __shared__ float Ws[64][17];
    int m0 = blockIdx.y * 64;
    int n0 = blockIdx.x * 64;
    int tid = threadIdx.x;
    int ty = tid >> 4, tx = tid & 15;
    float acc[4][4] = {};
    for (int k0 = 0; k0 < K; k0 += 16) {
#pragma unroll
        for (int i = 0; i < 4; i++) {
            int idx = tid + i * 256;
            int r = idx >> 4, c = idx & 15;
            As[r][c] = A[(size_t)(m0 + r) * K + k0 + c];
            Ws[r][c] = W[(size_t)(n0 + r) * K + k0 + c];
        }
        __syncthreads();
#pragma unroll
        for (int kk = 0; kk < 16; kk++) {
            float a[4], w[4];
#pragma unroll
            for (int i = 0; i < 4; i++) a[i] = As[ty * 4 + i][kk];
#pragma unroll
            for (int j = 0; j < 4; j++) w[j] = Ws[tx * 4 + j][kk];
#pragma unroll
            for (int i = 0; i < 4; i++)
#pragma unroll
                for (int j = 0; j < 4; j++) acc[i][j] += a[i] * w[j];
        }
        __syncthreads();
    }
#pragma unroll
    for (int i = 0; i < 4; i++) {
#pragma unroll
        for (int j = 0; j < 4; j++) {
            int m = m0 + ty * 4 + i, n = n0 + tx * 4 + j;
            float v = acc[i][j];
            if (MODE >= 1) v += bias[n];
            if (MODE == 2) v = 0.5f * v * (1.f + erff(v * 0.70710678118654752f));
            if (MODE == 3) v += res[(size_t)m * Nc + n];
            C[(size_t)m * Nc + n] = v;
        }
    }
}

// ---------------- per-row stats for fq, fk (warp per row of 64) ----------------
__global__ void stats_kernel(const float* __restrict__ f)
{
    int w = blockIdx.x * 8 + (threadIdx.x >> 5);
    int lane = threadIdx.x & 31;
    int which = w >> 15;           // 0 = q, 1 = k  (32768 rows each)
    int rem = w & 32767;
    int n = rem & 1023;
    int b = (rem >> 10) & 3;
    int h = rem >> 12;
    const float* src = f + (size_t)which * ROWS * DIM
                         + ((size_t)(b * Nn_ + n)) * DIM + h * DH;
    float x0 = src[lane], x1 = src[lane + 32];
    float s = x0 + x1, ss = x0 * x0 + x1 * x1;
#pragma unroll
    for (int off = 16; off; off >>= 1) {
        s  += __shfl_xor_sync(0xffffffffu, s, off);
        ss += __shfl_xor_sync(0xffffffffu, ss, off);
    }
    if (lane == 0) {
        int idx = (h * Bq + b) * Nn_ + n;
        float mean = s * (1.f / DH);
        float var  = (ss - s * s * (1.f / DH)) * (1.f / (DH - 1));  // ddof=1
        float inv  = rsqrtf(ss);                                    // 1/||row||
        if (which == 0) { g_qinv[idx] = inv; g_qmean[idx] = mean; g_qvar[idx] = var; }
        else            { g_kinv[idx] = inv; g_kmean[idx] = mean; g_kvar[idx] = var; }
    }
}

// ---------------- per-head global means over (b,n) ----------------
__global__ void headmean_kernel(const float* __restrict__ f)
{
    int id = blockIdx.x;            // 0..1023: which*512 + (h*64+d)
    int which = id >> 9;
    int hd = id & 511;
    const float* src = f + (size_t)which * ROWS * DIM + hd;
    float s = 0.f;
    for (int r = threadIdx.x; r < ROWS; r += 256) s += src[(size_t)r * DIM];
    __shared__ float rs[256];
    rs[threadIdx.x] = s;
    __syncthreads();
    for (int off = 128; off > 0; off >>= 1) {
        if (threadIdx.x < off) rs[threadIdx.x] += rs[threadIdx.x + off];
        __syncthreads();
    }
    if (threadIdx.x == 0) g_hg[id] = rs[0] * (1.f / ROWS);
}

// ---------------- gating MLP: 8 warps, one per head ----------------
__global__ void mlp_kernel(const float* __restrict__ W1, const float* __restrict__ b1,
                           const float* __restrict__ gg, const float* __restrict__ gb,
                           const float* __restrict__ W2, const float* __restrict__ b2)
{
    int h = threadIdx.x >> 5;
    int lane = threadIdx.x & 31;
    float h1[2];
#pragma unroll
    for (int t = 0; t < 2; t++) {
        int j = lane + t * 32;
        const float* wr = W1 + j * 128;
        float acc = b1[j];
        for (int i = 0; i < 64; i++) acc += g_hg[h * 64 + i] * wr[i];
        for (int i = 0; i < 64; i++) acc += g_hg[512 + h * 64 + i] * wr[64 + i];
        h1[t] = acc;
    }
    float s = h1[0] + h1[1], ss = h1[0] * h1[0] + h1[1] * h1[1];
#pragma unroll
    for (int off = 16; off; off >>= 1) {
        s  += __shfl_xor_sync(0xffffffffu, s, off);
        ss += __shfl_xor_sync(0xffffffffu, ss, off);
    }
    float mean = s * (1.f / 64.f);
    float var  = ss * (1.f / 64.f) - mean * mean;
    float inv  = rsqrtf(var + EPS);
    float hh[2];
#pragma unroll
    for (int t = 0; t < 2; t++) {
        int j = lane + t * 32;
        float v = (h1[t] - mean) * inv * gg[j] + gb[j];
        hh[t] = fmaxf(v, 0.f);
    }
    float lg[3];
#pragma unroll
    for (int c = 0; c < 3; c++) {
        float acc = hh[0] * W2[c * 64 + lane] + hh[1] * W2[c * 64 + lane + 32];
#pragma unroll
        for (int off = 16; off; off >>= 1) acc += __shfl_xor_sync(0xffffffffu, acc, off);
        lg[c] = acc + b2[c];
    }
    if (lane == 0) {
        float m = fmaxf(lg[0], fmaxf(lg[1], lg[2]));
        float e0 = expf(lg[0] - m), e1 = expf(lg[1] - m), e2 = expf(lg[2] - m);
        float inv_s = 1.f / (e0 + e1 + e2);
        g_w3[h * 3 + 0] = e0 * inv_s;
        g_w3[h * 3 + 1] = e1 * inv_s;
        g_w3[h * 3 + 2] = e2 * inv_s;
    }
}

// ---------------- dots GEMM + scores epilogue ----------------
// S[hb,n,m] = dots * (cw*qinv*kinv + covw/64) + (vw*qv*kv/64 - covw*mq*mk)
__global__ void dots_kernel()
{
    __shared__ float As[64][65];
    __shared__ float Bs[64][65];
    int hb = blockIdx.z;
    int h = hb >> 2, b = hb & 3;
    int n0 = blockIdx.y * 64, m0 = blockIdx.x * 64;
    const float* fq = g_f;
    const float* fk = g_f + (size_t)ROWS * DIM;
    int tid = threadIdx.x;
    int ty = tid >> 4, tx = tid & 15;
#pragma unroll
    for (int i = 0; i < 16; i++) {
        int idx = tid + i * 256;
        int r = idx >> 6, c = idx & 63;
        As[r][c] = fq[((size_t)(b * Nn_ + n0 + r)) * DIM + h * DH + c];
        Bs[r][c] = fk[((size_t)(b * Nn_ + m0 + r)) * DIM + h * DH + c];
    }
    __syncthreads();
    float acc[4][4] = {};
#pragma unroll 16
    for (int kk = 0; kk < 64; kk++) {
        float a[4], bv[4];
#pragma unroll
        for (int i = 0; i < 4; i++) a[i] = As[ty * 4 + i][kk];
#pragma unroll
        for (int j = 0; j < 4; j++) bv[j] = Bs[tx * 4 + j][kk];
#pragma unroll
        for (int i = 0; i < 4; i++)
#pragma unroll
            for (int j = 0; j < 4; j++) acc[i][j] += a[i] * bv[j];
    }
    float cw = g_w3[h * 3 + 0], covw = g_w3[h * 3 + 1], vw = g_w3[h * 3 + 2];
    int base = hb * Nn_;
#pragma unroll
    for (int i = 0; i < 4; i++) {
        int n = n0 + ty * 4 + i;
        float qi = g_qinv[base + n], qm = g_qmean[base + n], qv = g_qvar[base + n];
#pragma unroll
        for (int j = 0; j < 4; j++) {
            int m = m0 + tx * 4 + j;
            float coef = cw * qi * g_kinv[base + m] + covw * (1.f / DH);
            float add  = vw * qv * g_kvar[base + m] * (1.f / DH)
                       - covw * qm * g_kmean[base + m];
            g_S[((size_t)hb * Nn_ + n) * Nn_ + m] = acc[i][j] * coef + add;
        }
    }
}

// ---------------- O = S @ fv  (per hb: 1024x64x1024) ----------------
__global__ void av_kernel()
{
    __shared__ float As[64][17];
    __shared__ float Bs[16][64];
    int hb = blockIdx.z;
    int h = hb >> 2, b = hb & 3;
    int n0 = blockIdx.y * 64;
    const float* fv = g_f + 2 * (size_t)ROWS * DIM;
    int tid = threadIdx.x;
    int ty = tid >> 4, tx = tid & 15;
    float acc[4][4] = {};
    for (int k0 = 0; k0 < Nn_; k0 += 16) {
#pragma unroll
        for (int i = 0; i < 4; i++) {
            int idx = tid + i * 256;
            int r = idx >> 4, c = idx & 15;
            As[r][c] = g_S[((size_t)hb * Nn_ + n0 + r) * Nn_ + k0 + c];
        }
#pragma unroll
        for (int i = 0; i < 4; i++) {
            int idx = tid + i * 256;
            int kk = idx >> 6, d = idx & 63;
            Bs[kk][d] = fv[((size_t)(b * Nn_ + k0 + kk)) * DIM + h * DH + d];
        }
        __syncthreads();
#pragma unroll
        for (int kk = 0; kk < 16; kk++) {
            float a[4], bv[4];
#pragma unroll
            for (int i = 0; i < 4; i++) a[i] = As[ty * 4 + i][kk];
#pragma unroll
            for (int j = 0; j < 4; j++) bv[j] = Bs[kk][tx * 4 + j];
#pragma unroll
            for (int i = 0; i < 4; i++)
#pragma unroll
                for (int j = 0; j < 4; j++) acc[i][j] += a[i] * bv[j];
        }
        __syncthreads();
    }
#pragma unroll
    for (int i = 0; i < 4; i++)
#pragma unroll
        for (int j = 0; j < 4; j++)
            g_ao[((size_t)(b * Nn_ + n0 + ty * 4 + i)) * DIM + h * DH + tx * 4 + j] = acc[i][j];
}

// ---------------- launch ----------------
extern "C" void kernel_launch(void* const* d_in, const int* in_sizes, int n_in,
                              void* d_out, int out_size)
{
    const float* q    = (const float*)d_in[0];
    const float* k    = (const float*)d_in[1];
    const float* v    = (const float*)d_in[2];
    const float* Win  = (const float*)d_in[3];
    const float* Wout = (const float*)d_in[4];
    const float* bout = (const float*)d_in[5];
    const float* g1   = (const float*)d_in[6];
    const float* b1n  = (const float*)d_in[7];
    const float* g2   = (const float*)d_in[8];
    const float* b2n  = (const float*)d_in[9];
    const float* Wup  = (const float*)d_in[10];
    const float* bup  = (const float*)d_in[11];
    const float* Wdn  = (const float*)d_in[12];
    const float* bdn  = (const float*)d_in[13];
    const float* wpW1 = (const float*)d_in[14];
    const float* wpb1 = (const float*)d_in[15];
    const float* wpg  = (const float*)d_in[16];
    const float* wpb  = (const float*)d_in[17];
    const float* wpW2 = (const float*)d_in[18];
    const float* wpb2 = (const float*)d_in[19];
    float* out = (float*)d_out;

    float* xn;  cudaGetSymbolAddress((void**)&xn,  g_xn);
    float* f;   cudaGetSymbolAddress((void**)&f,   g_f);
    float* ao;  cudaGetSymbolAddress((void**)&ao,  g_ao);
    float* q2;  cudaGetSymbolAddress((void**)&q2,  g_q2);
    float* xn2; cudaGetSymbolAddress((void**)&xn2, g_xn2);
    float* u;   cudaGetSymbolAddress((void**)&u,   g_u);

    // 1. LN of q,k,v
    ln_kernel<<<ROWS, 256>>>(q, g1, b1n, xn);
    ln_kernel<<<ROWS, 256>>>(k, g1, b1n, xn + (size_t)ROWS * DIM);
    ln_kernel<<<ROWS, 256>>>(v, g1, b1n, xn + 2 * (size_t)ROWS * DIM);

    // 2. fused projection for all three: [3*4096, 512] @ Win^T
    gemm_kernel<0><<<dim3(DIM / 64, 3 * ROWS / 64), 256>>>(xn, Win, nullptr, nullptr, f,
                                                           3 * ROWS, DIM, DIM);

    // 3. per-row stats + head means + gating MLP
    stats_kernel<<<(2 * HB * Nn_) / 8, 256>>>(f);
    headmean_kernel<<<2 * Hh * DH, 256>>>(f);
    mlp_kernel<<<1, 256>>>(wpW1, wpb1, wpg, wpb, wpW2, wpb2);

    // 4. scores (QK^T with fused 3-component epilogue)
    dots_kernel<<<dim3(Nn_ / 64, Nn_ / 64, HB), 256>>>();

    // 5. O = S @ V
    av_kernel<<<dim3(1, Nn_ / 64, HB), 256>>>();

    // 6. attn out proj + residual -> q2
    gemm_kernel<3><<<dim3(DIM / 64, ROWS / 64), 256>>>(ao, Wout, bout, q, q2,
                                                       ROWS, DIM, DIM);

    // 7. LN2
    ln_kernel<<<ROWS, 256>>>(q2, g2, b2n, xn2);

    // 8. MLP up + gelu
    gemm_kernel<2><<<dim3(MLPD / 64, ROWS / 64), 256>>>(xn2, Wup, bup, nullptr, u,
                                                        ROWS, MLPD, DIM);

    // 9. MLP down + residual -> out
    gemm_kernel<3><<<dim3(DIM / 64, ROWS / 64), 256>>>(u, Wdn, bdn, q2, out,
                                                       ROWS, DIM, MLPD);
}

// round 2
// speedup vs baseline: 1.7014x; 1.7014x over previous
#include <cuda_runtime.h>
#include <cuda_bf16.h>
#include <math.h>

// ---------------- problem constants ----------------
#define Bq   4
#define Nn_  1024
#define DIM  512
#define Hh   8
#define DH   64
#define MLPD 2048
#define ROWS (Bq * Nn_)            // 4096 token rows
#define HB   (Hh * Bq)             // 32 attention batches
#define EPS  1e-5f

typedef unsigned long long u64;

// ---------------- f32x2 packed-FMA helpers (sm_103a FFMA2) ----------------
__device__ __forceinline__ u64 pk2(float x, float y){
    u64 r; asm("mov.b64 %0,{%1,%2};" : "=l"(r) : "f"(x), "f"(y)); return r;
}
__device__ __forceinline__ void unpk(u64 d, float& x, float& y){
    asm("mov.b64 {%0,%1},%2;" : "=f"(x), "=f"(y) : "l"(d));
}
__device__ __forceinline__ void fma2(u64& d, u64 a, u64 b){
    asm("fma.rn.f32x2 %0,%1,%2,%0;" : "+l"(d) : "l"(a), "l"(b));
}
__device__ __forceinline__ void lds_2x64(u64& x, u64& y, const float* p){
    unsigned s = (unsigned)__cvta_generic_to_shared((void*)p);
    asm volatile("ld.shared.v2.b64 {%0,%1},[%2];" : "=l"(x), "=l"(y) : "r"(s));
}

// ---------------- device scratch (no allocs allowed) ----------------
__device__ float g_xn [3 * ROWS * DIM];
__device__ float g_f  [3 * ROWS * DIM];
__device__ float g_S  [(size_t)HB * Nn_ * Nn_];
__device__ float g_ao [ROWS * DIM];
__device__ float g_q2 [ROWS * DIM];
__device__ float g_xn2[ROWS * DIM];
__device__ float g_u  [ROWS * MLPD];
__device__ float g_qinv [HB * Nn_];
__device__ float g_qmean[HB * Nn_];
__device__ float g_qvar [HB * Nn_];
__device__ float g_kinv [HB * Nn_];
__device__ float g_kmean[HB * Nn_];
__device__ float g_kvar [HB * Nn_];
__device__ float g_hg [2 * Hh * DH];
__device__ float g_w3 [Hh * 3];

// ---------------- layernorm over rows of 512 ----------------
__global__ void ln_kernel(const float* __restrict__ x, const float* __restrict__ g,
                          const float* __restrict__ bb, float* __restrict__ y)
{
    int row = blockIdx.x;
    int tid = threadIdx.x;
    const float* xr = x + (size_t)row * DIM;
    float v0 = xr[tid], v1 = xr[tid + 256];
    float s = v0 + v1, ss = v0 * v0 + v1 * v1;
    __shared__ float rs[256], rss[256];
    rs[tid] = s; rss[tid] = ss;
    __syncthreads();
    for (int off = 128; off > 0; off >>= 1) {
        if (tid < off) { rs[tid] += rs[tid + off]; rss[tid] += rss[tid + off]; }
        __syncthreads();
    }
    float mean = rs[0] * (1.f / DIM);
    float var  = rss[0] * (1.f / DIM) - mean * mean;
    float inv  = rsqrtf(var + EPS);
    float* yr = y + (size_t)row * DIM;
    yr[tid]       = (v0 - mean) * inv * g[tid]       + bb[tid];
    yr[tid + 256] = (v1 - mean) * inv * g[tid + 256] + bb[tid + 256];
}

// ---------------- FFMA2 GEMM: C = A[M,K] @ W[N,K]^T, 128x128 tile ----------------
// MODE: 0 plain, 1 +bias, 2 +bias+gelu(exact), 3 +bias+residual
template <int MODE>
__global__ void __launch_bounds__(256) gemm2_kernel(
    const float* __restrict__ A, const float* __restrict__ W,
    const float* __restrict__ bias, const float* __restrict__ res,
    float* __restrict__ C, int M, int Nc, int K)
{
    __shared__ __align__(16) float As[2][16][132];
    __shared__ __align__(16) float Bs[2][16][132];
    const int tid = threadIdx.x;
    const int m0 = blockIdx.y * 128, n0 = blockIdx.x * 128;
    const int ty = tid >> 4, tx = tid & 15;
    const int lr = tid >> 2, lc = (tid & 3) * 4;

    u64 acc[4][8];
#pragma unroll
    for (int i = 0; i < 4; i++)
#pragma unroll
        for (int j = 0; j < 8; j++) acc[i][j] = 0ull;

    const float* Ap0 = A + (size_t)(m0 + lr) * K + lc;
    const float* Ap1 = A + (size_t)(m0 + lr + 64) * K + lc;
    const float* Wp0 = W + (size_t)(n0 + lr) * K + lc;
    const float* Wp1 = W + (size_t)(n0 + lr + 64) * K + lc;

    float4 ra0 = *(const float4*)Ap0;
    float4 ra1 = *(const float4*)Ap1;
    float4 rb0 = *(const float4*)Wp0;
    float4 rb1 = *(const float4*)Wp1;

    As[0][lc+0][lr]    = ra0.x; As[0][lc+1][lr]    = ra0.y; As[0][lc+2][lr]    = ra0.z; As[0][lc+3][lr]    = ra0.w;
    As[0][lc+0][lr+64] = ra1.x; As[0][lc+1][lr+64] = ra1.y; As[0][lc+2][lr+64] = ra1.z; As[0][lc+3][lr+64] = ra1.w;
    Bs[0][lc+0][lr]    = rb0.x; Bs[0][lc+1][lr]    = rb0.y; Bs[0][lc+2][lr]    = rb0.z; Bs[0][lc+3][lr]    = rb0.w;
    Bs[0][lc+0][lr+64] = rb1.x; Bs[0][lc+1][lr+64] = rb1.y; Bs[0][lc+2][lr+64] = rb1.z; Bs[0][lc+3][lr+64] = rb1.w;

    int buf = 0;
    for (int k0 = 16; k0 <= K; k0 += 16) {
        __syncthreads();
        const bool more = (k0 < K);
        if (more) {
            ra0 = *(const float4*)(Ap0 + k0);
            ra1 = *(const float4*)(Ap1 + k0);
            rb0 = *(const float4*)(Wp0 + k0);
            rb1 = *(const float4*)(Wp1 + k0);
        }
#pragma unroll
        for (int kk = 0; kk < 16; kk++) {
            u64 a2[4];
            lds_2x64(a2[0], a2[1], &As[buf][kk][ty*8]);
            lds_2x64(a2[2], a2[3], &As[buf][kk][ty*8+4]);
            float bb8[8];
            *(float4*)&bb8[0] = *(const float4*)&Bs[buf][kk][tx*8];
            *(float4*)&bb8[4] = *(const float4*)&Bs[buf][kk][tx*8+4];
#pragma unroll
            for (int j = 0; j < 8; j++) {
                u64 bj = pk2(bb8[j], bb8[j]);
#pragma unroll
                for (int i = 0; i < 4; i++) fma2(acc[i][j], a2[i], bj);
            }
        }
        if (more) {
            int nb = buf ^ 1;
            As[nb][lc+0][lr]    = ra0.x; As[nb][lc+1][lr]    = ra0.y; As[nb][lc+2][lr]    = ra0.z; As[nb][lc+3][lr]    = ra0.w;
            As[nb][lc+0][lr+64] = ra1.x; As[nb][lc+1][lr+64] = ra1.y; As[nb][lc+2][lr+64] = ra1.z; As[nb][lc+3][lr+64] = ra1.w;
            Bs[nb][lc+0][lr]    = rb0.x; Bs[nb][lc+1][lr]    = rb0.y; Bs[nb][lc+2][lr]    = rb0.z; Bs[nb][lc+3][lr]    = rb0.w;
            Bs[nb][lc+0][lr+64] = rb1.x; Bs[nb][lc+1][lr+64] = rb1.y; Bs[nb][lc+2][lr+64] = rb1.z; Bs[nb][lc+3][lr+64] = rb1.w;
        }
        buf ^= 1;
    }

    const int n = n0 + tx * 8;
    float bv[8];
    if (MODE >= 1) {
        *(float4*)&bv[0] = *(const float4*)&bias[n];
        *(float4*)&bv[4] = *(const float4*)&bias[n + 4];
    }
#pragma unroll
    for (int i = 0; i < 4; i++) {
        const int r0 = m0 + ty * 8 + 2 * i;
        float c0[8], c1[8];
#pragma unroll
        for (int j = 0; j < 8; j++) unpk(acc[i][j], c0[j], c1[j]);
        if (MODE >= 1) {
#pragma unroll
            for (int j = 0; j < 8; j++) { c0[j] += bv[j]; c1[j] += bv[j]; }
        }
        if (MODE == 2) {
#pragma unroll
            for (int j = 0; j < 8; j++) {
                c0[j] = 0.5f * c0[j] * (1.f + erff(c0[j] * 0.70710678118654752f));
                c1[j] = 0.5f * c1[j] * (1.f + erff(c1[j] * 0.70710678118654752f));
            }
        }
        if (MODE == 3) {
            float r0v[8], r1v[8];
            *(float4*)&r0v[0] = *(const float4*)(res + (size_t)r0 * Nc + n);
            *(float4*)&r0v[4] = *(const float4*)(res + (size_t)r0 * Nc + n + 4);
            *(float4*)&r1v[0] = *(const float4*)(res + (size_t)(r0+1) * Nc + n);
            *(float4*)&r1v[4] = *(const float4*)(res + (size_t)(r0+1) * Nc + n + 4);
#pragma unroll
            for (int j = 0; j < 8; j++) { c0[j] += r0v[j]; c1[j] += r1v[j]; }
        }
        *(float4*)(C + (size_t)r0 * Nc + n)         = make_float4(c0[0], c0[1], c0[2], c0[3]);
        *(float4*)(C + (size_t)r0 * Nc + n + 4)     = make_float4(c0[4], c0[5], c0[6], c0[7]);
        *(float4*)(C + (size_t)(r0+1) * Nc + n)     = make_float4(c1[0], c1[1], c1[2], c1[3]);
        *(float4*)(C + (size_t)(r0+1) * Nc + n + 4) = make_float4(c1[4], c1[5], c1[6], c1[7]);
    }
}

// ---------------- per-row stats for fq, fk ----------------
__global__ void stats_kernel(const float* __restrict__ f)
{
    int w = blockIdx.x * 8 + (threadIdx.x >> 5);
    int lane = threadIdx.x & 31;
    int which = w >> 15;
    int rem = w & 32767;
    int n = rem & 1023;
    int b = (rem >> 10) & 3;
    int h = rem >> 12;
    const float* src = f + (size_t)which * ROWS * DIM
                         + ((size_t)(b * Nn_ + n)) * DIM + h * DH;
    float x0 = src[lane], x1 = src[lane + 32];
    float s = x0 + x1, ss = x0 * x0 + x1 * x1;
#pragma unroll
    for (int off = 16; off; off >>= 1) {
        s  += __shfl_xor_sync(0xffffffffu, s, off);
        ss += __shfl_xor_sync(0xffffffffu, ss, off);
    }
    if (lane == 0) {
        int idx = (h * Bq + b) * Nn_ + n;
        float mean = s * (1.f / DH);
        float var  = (ss - s * s * (1.f / DH)) * (1.f / (DH - 1));
        float inv  = rsqrtf(ss);
        if (which == 0) { g_qinv[idx] = inv; g_qmean[idx] = mean; g_qvar[idx] = var; }
        else            { g_kinv[idx] = inv; g_kmean[idx] = mean; g_kvar[idx] = var; }
    }
}

// ---------------- per-head global means ----------------
__global__ void headmean_kernel(const float* __restrict__ f)
{
    int id = blockIdx.x;
    int which = id >> 9;
    int hd = id & 511;
    const float* src = f + (size_t)which * ROWS * DIM + hd;
    float s = 0.f;
    for (int r = threadIdx.x; r < ROWS; r += 256) s += src[(size_t)r * DIM];
    __shared__ float rs[256];
    rs[threadIdx.x] = s;
    __syncthreads();
    for (int off = 128; off > 0; off >>= 1) {
        if (threadIdx.x < off) rs[threadIdx.x] += rs[threadIdx.x + off];
        __syncthreads();
    }
    if (threadIdx.x == 0) g_hg[id] = rs[0] * (1.f / ROWS);
}

// ---------------- gating MLP ----------------
__global__ void mlp_kernel(const float* __restrict__ W1, const float* __restrict__ b1,
                           const float* __restrict__ gg, const float* __restrict__ gb,
                           const float* __restrict__ W2, const float* __restrict__ b2)
{
    int h = threadIdx.x >> 5;
    int lane = threadIdx.x & 31;
    float h1[2];
#pragma unroll
    for (int t = 0; t < 2; t++) {
        int j = lane + t * 32;
        const float* wr = W1 + j * 128;
        float acc = b1[j];
        for (int i = 0; i < 64; i++) acc += g_hg[h * 64 + i] * wr[i];
        for (int i = 0; i < 64; i++) acc += g_hg[512 + h * 64 + i] * wr[64 + i];
        h1[t] = acc;
    }
    float s = h1[0] + h1[1], ss = h1[0] * h1[0] + h1[1] * h1[1];
#pragma unroll
    for (int off = 16; off; off >>= 1) {
        s  += __shfl_xor_sync(0xffffffffu, s, off);
        ss += __shfl_xor_sync(0xffffffffu, ss, off);
    }
    float mean = s * (1.f / 64.f);
    float var  = ss * (1.f / 64.f) - mean * mean;
    float inv  = rsqrtf(var + EPS);
    float hh[2];
#pragma unroll
    for (int t = 0; t < 2; t++) {
        int j = lane + t * 32;
        float v = (h1[t] - mean) * inv * gg[j] + gb[j];
        hh[t] = fmaxf(v, 0.f);
    }
    float lg[3];
#pragma unroll
    for (int c = 0; c < 3; c++) {
        float acc = hh[0] * W2[c * 64 + lane] + hh[1] * W2[c * 64 + lane + 32];
#pragma unroll
        for (int off = 16; off; off >>= 1) acc += __shfl_xor_sync(0xffffffffu, acc, off);
        lg[c] = acc + b2[c];
    }
    if (lane == 0) {
        float m = fmaxf(lg[0], fmaxf(lg[1], lg[2]));
        float e0 = expf(lg[0] - m), e1 = expf(lg[1] - m), e2 = expf(lg[2] - m);
        float inv_s = 1.f / (e0 + e1 + e2);
        g_w3[h * 3 + 0] = e0 * inv_s;
        g_w3[h * 3 + 1] = e1 * inv_s;
        g_w3[h * 3 + 2] = e2 * inv_s;
    }
}

// ---------------- dots GEMM + scores epilogue (FFMA2, 128x128, K=64) ----------------
__global__ void __launch_bounds__(256) dots2_kernel()
{
    __shared__ __align__(16) float As[2][16][132];
    __shared__ __align__(16) float Bs[2][16][132];
    const int tid = threadIdx.x;
    const int hb = blockIdx.z, h = hb >> 2, b = hb & 3;
    const int n0 = blockIdx.y * 128, m0 = blockIdx.x * 128;
    const int ty = tid >> 4, tx = tid & 15;
    const int lr = tid >> 2, lc = (tid & 3) * 4;

    const float* fq = g_f;
    const float* fk = g_f + (size_t)ROWS * DIM;
    const float* Ap0 = fq + (size_t)(b * Nn_ + n0 + lr) * DIM + h * DH + lc;
    const float* Ap1 = Ap0 + (size_t)64 * DIM;
    const float* Bp0 = fk + (size_t)(b * Nn_ + m0 + lr) * DIM + h * DH + lc;
    const float* Bp1 = Bp0 + (size_t)64 * DIM;

    u64 acc[4][8];
#pragma unroll
    for (int i = 0; i < 4; i++)
#pragma unroll
        for (int j = 0; j < 8; j++) acc[i][j] = 0ull;

    float4 ra0 = *(const float4*)Ap0;
    float4 ra1 = *(const float4*)Ap1;
    float4 rb0 = *(const float4*)Bp0;
    float4 rb1 = *(const float4*)Bp1;
    As[0][lc+0][lr]    = ra0.x; As[0][lc+1][lr]    = ra0.y; As[0][lc+2][lr]    = ra0.z; As[0][lc+3][lr]    = ra0.w;
    As[0][lc+0][lr+64] = ra1.x; As[0][lc+1][lr+64] = ra1.y; As[0][lc+2][lr+64] = ra1.z; As[0][lc+3][lr+64] = ra1.w;
    Bs[0][lc+0][lr]    = rb0.x; Bs[0][lc+1][lr]    = rb0.y; Bs[0][lc+2][lr]    = rb0.z; Bs[0][lc+3][lr]    = rb0.w;
    Bs[0][lc+0][lr+64] = rb1.x; Bs[0][lc+1][lr+64] = rb1.y; Bs[0][lc+2][lr+64] = rb1.z; Bs[0][lc+3][lr+64] = rb1.w;

    int buf = 0;
    for (int k0 = 16; k0 <= DH; k0 += 16) {
        __syncthreads();
        const bool more = (k0 < DH);
        if (more) {
            ra0 = *(const float4*)(Ap0 + k0);
            ra1 = *(const float4*)(Ap1 + k0);
            rb0 = *(const float4*)(Bp0 + k0);
            rb1 = *(const float4*)(Bp1 + k0);
        }
#pragma unroll
        for (int kk = 0; kk < 16; kk++) {
            u64 a2[4];
            lds_2x64(a2[0], a2[1], &As[buf][kk][ty*8]);
            lds_2x64(a2[2], a2[3], &As[buf][kk][ty*8+4]);
            float bb8[8];
            *(float4*)&bb8[0] = *(const float4*)&Bs[buf][kk][tx*8];
            *(float4*)&bb8[4] = *(const float4*)&Bs[buf][kk][tx*8+4];
#pragma unroll
            for (int j = 0; j < 8; j++) {
                u64 bj = pk2(bb8[j], bb8[j]);
#pragma unroll
                for (int i = 0; i < 4; i++) fma2(acc[i][j], a2[i], bj);
            }
        }
        if (more) {
            int nb = buf ^ 1;
            As[nb][lc+0][lr]    = ra0.x; As[nb][lc+1][lr]    = ra0.y; As[nb][lc+2][lr]    = ra0.z; As[nb][lc+3][lr]    = ra0.w;
            As[nb][lc+0][lr+64] = ra1.x; As[nb][lc+1][lr+64] = ra1.y; As[nb][lc+2][lr+64] = ra1.z; As[nb][lc+3][lr+64] = ra1.w;
            Bs[nb][lc+0][lr]    = rb0.x; Bs[nb][lc+1][lr]    = rb0.y; Bs[nb][lc+2][lr]    = rb0.z; Bs[nb][lc+3][lr]    = rb0.w;
            Bs[nb][lc+0][lr+64] = rb1.x; Bs[nb][lc+1][lr+64] = rb1.y; Bs[nb][lc+2][lr+64] = rb1.z; Bs[nb][lc+3][lr+64] = rb1.w;
        }
        buf ^= 1;
    }

    const float cw = g_w3[h * 3 + 0], covw = g_w3[h * 3 + 1], vw = g_w3[h * 3 + 2];
    const int base = hb * Nn_;
    const int mcol = m0 + tx * 8;
    float ki[8], km[8], kv[8];
    *(float4*)&ki[0] = *(const float4*)&g_kinv [base + mcol];
    *(float4*)&ki[4] = *(const float4*)&g_kinv [base + mcol + 4];
    *(float4*)&km[0] = *(const float4*)&g_kmean[base + mcol];
    *(float4*)&km[4] = *(const float4*)&g_kmean[base + mcol + 4];
    *(float4*)&kv[0] = *(const float4*)&g_kvar [base + mcol];
    *(float4*)&kv[4] = *(const float4*)&g_kvar [base + mcol + 4];

#pragma unroll
    for (int i = 0; i < 4; i++) {
        const int r0 = n0 + ty * 8 + 2 * i;
        float qi0 = g_qinv[base + r0],     qm0 = g_qmean[base + r0],     qv0 = g_qvar[base + r0];
        float qi1 = g_qinv[base + r0 + 1], qm1 = g_qmean[base + r0 + 1], qv1 = g_qvar[base + r0 + 1];
        float c0[8], c1[8];
#pragma unroll
        for (int j = 0; j < 8; j++) {
            float x, y; unpk(acc[i][j], x, y);
            c0[j] = x * (cw * qi0 * ki[j] + covw * (1.f / DH))
                  + vw * qv0 * kv[j] * (1.f / DH) - covw * qm0 * km[j];
            c1[j] = y * (cw * qi1 * ki[j] + covw * (1.f / DH))
                  + vw * qv1 * kv[j] * (1.f / DH) - covw * qm1 * km[j];
        }
        float* s0 = g_S + ((size_t)base + r0) * Nn_ + mcol;
        float* s1 = g_S + ((size_t)base + r0 + 1) * Nn_ + mcol;
        *(float4*)(s0)     = make_float4(c0[0], c0[1], c0[2], c0[3]);
        *(float4*)(s0 + 4) = make_float4(c0[4], c0[5], c0[6], c0[7]);
        *(float4*)(s1)     = make_float4(c1[0], c1[1], c1[2], c1[3]);
        *(float4*)(s1 + 4) = make_float4(c1[4], c1[5], c1[6], c1[7]);
    }
}

// ---------------- O = S @ fv  (FFMA2, 128x64 tile, K=1024) ----------------
__global__ void __launch_bounds__(256) av2_kernel()
{
    __shared__ __align__(16) float As[2][16][132];
    __shared__ __align__(16) float Bs[2][16][68];
    const int tid = threadIdx.x;
    const int hb = blockIdx.z, h = hb >> 2, b = hb & 3;
    const int n0 = blockIdx.y * 128;
    const int ty = tid >> 4, tx = tid & 15;
    const int lr = tid >> 2, lc = (tid & 3) * 4;
    const int kB = tid >> 4, c4 = (tid & 15) * 4;

    const float* fv = g_f + 2 * (size_t)ROWS * DIM;
    const float* Sp0 = g_S + ((size_t)hb * Nn_ + n0 + lr) * Nn_ + lc;
    const float* Sp1 = Sp0 + (size_t)64 * Nn_;
    const float* Vp  = fv + (size_t)(b * Nn_ + kB) * DIM + h * DH + c4;

    u64 acc[4][4];
#pragma unroll
    for (int i = 0; i < 4; i++)
#pragma unroll
        for (int j = 0; j < 4; j++) acc[i][j] = 0ull;

    float4 ra0 = *(const float4*)Sp0;
    float4 ra1 = *(const float4*)Sp1;
    float4 rb  = *(const float4*)Vp;
    As[0][lc+0][lr]    = ra0.x; As[0][lc+1][lr]    = ra0.y; As[0][lc+2][lr]    = ra0.z; As[0][lc+3][lr]    = ra0.w;
    As[0][lc+0][lr+64] = ra1.x; As[0][lc+1][lr+64] = ra1.y; As[0][lc+2][lr+64] = ra1.z; As[0][lc+3][lr+64] = ra1.w;
    *(float4*)&Bs[0][kB][c4] = rb;

    int buf = 0;
    for (int k0 = 16; k0 <= Nn_; k0 += 16) {
        __syncthreads();
        const bool more = (k0 < Nn_);
        if (more) {
            ra0 = *(const float4*)(Sp0 + k0);
            ra1 = *(const float4*)(Sp1 + k0);
            rb  = *(const float4*)(Vp + (size_t)k0 * DIM);
        }
#pragma unroll
        for (int kk = 0; kk < 16; kk++) {
            u64 a2[4];
            lds_2x64(a2[0], a2[1], &As[buf][kk][ty*8]);
            lds_2x64(a2[2], a2[3], &As[buf][kk][ty*8+4]);
            float bb4[4];
            *(float4*)&bb4[0] = *(const float4*)&Bs[buf][kk][tx*4];
#pragma unroll
            for (int j = 0; j < 4; j++) {
                u64 bj = pk2(bb4[j], bb4[j]);
#pragma unroll
                for (int i = 0; i < 4; i++) fma2(acc[i][j], a2[i], bj);
            }
        }
        if (more) {
            int nb = buf ^ 1;
            As[nb][lc+0][lr]    = ra0.x; As[nb][lc+1][lr]    = ra0.y; As[nb][lc+2][lr]    = ra0.z; As[nb][lc+3][lr]    = ra0.w;
            As[nb][lc+0][lr+64] = ra1.x; As[nb][lc+1][lr+64] = ra1.y; As[nb][lc+2][lr+64] = ra1.z; As[nb][lc+3][lr+64] = ra1.w;
            *(float4*)&Bs[nb][kB][c4] = rb;
        }
        buf ^= 1;
    }

#pragma unroll
    for (int i = 0; i < 4; i++) {
        const int r0 = n0 + ty * 8 + 2 * i;
        float c0[4], c1[4];
#pragma unroll
        for (int j = 0; j < 4; j++) unpk(acc[i][j], c0[j], c1[j]);
        float* o0 = g_ao + (size_t)(b * Nn_ + r0) * DIM + h * DH + tx * 4;
        float* o1 = o0 + DIM;
        *(float4*)o0 = make_float4(c0[0], c0[1], c0[2], c0[3]);
        *(float4*)o1 = make_float4(c1[0], c1[1], c1[2], c1[3]);
    }
}

// ---------------- launch ----------------
extern "C" void kernel_launch(void* const* d_in, const int* in_sizes, int n_in,
                              void* d_out, int out_size)
{
    const float* q    = (const float*)d_in[0];
    const float* k    = (const float*)d_in[1];
    const float* v    = (const float*)d_in[2];
    const float* Win  = (const float*)d_in[3];
    const float* Wout = (const float*)d_in[4];
    const float* bout = (const float*)d_in[5];
    const float* g1   = (const float*)d_in[6];
    const float* b1n  = (const float*)d_in[7];
    const float* g2   = (const float*)d_in[8];
    const float* b2n  = (const float*)d_in[9];
    const float* Wup  = (const float*)d_in[10];
    const float* bup  = (const float*)d_in[11];
    const float* Wdn  = (const float*)d_in[12];
    const float* bdn  = (const float*)d_in[13];
    const float* wpW1 = (const float*)d_in[14];
    const float* wpb1 = (const float*)d_in[15];
    const float* wpg  = (const float*)d_in[16];
    const float* wpb  = (const float*)d_in[17];
    const float* wpW2 = (const float*)d_in[18];
    const float* wpb2 = (const float*)d_in[19];
    float* out = (float*)d_out;

    float* xn;  cudaGetSymbolAddress((void**)&xn,  g_xn);
    float* f;   cudaGetSymbolAddress((void**)&f,   g_f);
    float* ao;  cudaGetSymbolAddress((void**)&ao,  g_ao);
    float* q2;  cudaGetSymbolAddress((void**)&q2,  g_q2);
    float* xn2; cudaGetSymbolAddress((void**)&xn2, g_xn2);
    float* u;   cudaGetSymbolAddress((void**)&u,   g_u);

    // 1. LN of q,k,v
    ln_kernel<<<ROWS, 256>>>(q, g1, b1n, xn);
    ln_kernel<<<ROWS, 256>>>(k, g1, b1n, xn + (size_t)ROWS * DIM);
    ln_kernel<<<ROWS, 256>>>(v, g1, b1n, xn + 2 * (size_t)ROWS * DIM);

    // 2. fused projection: [3*4096, 512] @ Win^T
    gemm2_kernel<0><<<dim3(DIM / 128, 3 * ROWS / 128), 256>>>(xn, Win, nullptr, nullptr, f,
                                                              3 * ROWS, DIM, DIM);

    // 3. per-row stats + head means + gating MLP
    stats_kernel<<<(2 * HB * Nn_) / 8, 256>>>(f);
    headmean_kernel<<<2 * Hh * DH, 256>>>(f);
    mlp_kernel<<<1, 256>>>(wpW1, wpb1, wpg, wpb, wpW2, wpb2);

    // 4. scores (QK^T with fused 3-component epilogue)
    dots2_kernel<<<dim3(Nn_ / 128, Nn_ / 128, HB), 256>>>();

    // 5. O = S @ V
    av2_kernel<<<dim3(1, Nn_ / 128, HB), 256>>>();

    // 6. attn out proj + residual -> q2
    gemm2_kernel<3><<<dim3(DIM / 128, ROWS / 128), 256>>>(ao, Wout, bout, q, q2,
                                                          ROWS, DIM, DIM);

    // 7. LN2
    ln_kernel<<<ROWS, 256>>>(q2, g2, b2n, xn2);

    // 8. MLP up + gelu
    gemm2_kernel<2><<<dim3(MLPD / 128, ROWS / 128), 256>>>(xn2, Wup, bup, nullptr, u,
                                                           ROWS, MLPD, DIM);

    // 9. MLP down + residual -> out
    gemm2_kernel<3><<<dim3(DIM / 128, ROWS / 128), 256>>>(u, Wdn, bdn, q2, out,
                                                          ROWS, DIM, MLPD);
}

// round 3
// speedup vs baseline: 2.9436x; 1.7301x over previous
#include <cuda_runtime.h>
#include <cuda_bf16.h>
#include <math.h>

// ---------------- problem constants ----------------
#define Bq   4
#define Nn_  1024
#define DIM  512
#define Hh   8
#define DH   64
#define MLPD 2048
#define ROWS (Bq * Nn_)            // 4096 token rows
#define HB   (Hh * Bq)             // 32 attention batches
#define EPS  1e-5f

// ---------------- tf32 mma helpers ----------------
__device__ __forceinline__ float t32f(float x){
    unsigned r; asm("cvt.rna.tf32.f32 %0,%1;" : "=r"(r) : "f"(x));
    return __uint_as_float(r);
}
__device__ __forceinline__ void mma8(float* c, const unsigned* a, const unsigned* b){
    asm("mma.sync.aligned.m16n8k8.row.col.f32.tf32.tf32.f32 "
        "{%0,%1,%2,%3},{%4,%5,%6,%7},{%8,%9},{%0,%1,%2,%3};"
        : "+f"(c[0]), "+f"(c[1]), "+f"(c[2]), "+f"(c[3])
        : "r"(a[0]), "r"(a[1]), "r"(a[2]), "r"(a[3]), "r"(b[0]), "r"(b[1]));
}

// ---------------- device scratch (no allocs allowed) ----------------
__device__ float g_xn [3 * ROWS * DIM];
__device__ float g_f  [3 * ROWS * DIM];
__device__ float g_S  [(size_t)HB * Nn_ * Nn_];
__device__ float g_ao [ROWS * DIM];
__device__ float g_q2 [ROWS * DIM];
__device__ float g_xn2[ROWS * DIM];
__device__ float g_u  [ROWS * MLPD];
__device__ float g_qinv [HB * Nn_];
__device__ float g_qmean[HB * Nn_];
__device__ float g_qvar [HB * Nn_];
__device__ float g_kinv [HB * Nn_];
__device__ float g_kmean[HB * Nn_];
__device__ float g_kvar [HB * Nn_];
__device__ float g_hg [2 * Hh * DH];
__device__ float g_w3 [Hh * 3];

// ---------------- layernorm over rows of 512 ----------------
__global__ void ln_kernel(const float* __restrict__ x, const float* __restrict__ g,
                          const float* __restrict__ bb, float* __restrict__ y)
{
    int row = blockIdx.x;
    int tid = threadIdx.x;
    const float* xr = x + (size_t)row * DIM;
    float v0 = xr[tid], v1 = xr[tid + 256];
    float s = v0 + v1, ss = v0 * v0 + v1 * v1;
    __shared__ float rs[256], rss[256];
    rs[tid] = s; rss[tid] = ss;
    __syncthreads();
    for (int off = 128; off > 0; off >>= 1) {
        if (tid < off) { rs[tid] += rs[tid + off]; rss[tid] += rss[tid + off]; }
        __syncthreads();
    }
    float mean = rs[0] * (1.f / DIM);
    float var  = rss[0] * (1.f / DIM) - mean * mean;
    float inv  = rsqrtf(var + EPS);
    float* yr = y + (size_t)row * DIM;
    yr[tid]       = (v0 - mean) * inv * g[tid]       + bb[tid];
    yr[tid + 256] = (v1 - mean) * inv * g[tid + 256] + bb[tid + 256];
}

// ================ tf32 tensor-core GEMM: C = A[M,K] @ W[N,K]^T ================
// 128x128 CTA tile, BK=16, 8 warps each 64x32.
// MODE: 0 plain, 1 +bias, 2 +bias+gelu(exact), 3 +bias+residual
template <int MODE>
__global__ void __launch_bounds__(256) tmm_kernel(
    const float* __restrict__ A, const float* __restrict__ W,
    const float* __restrict__ bias, const float* __restrict__ res,
    float* __restrict__ C, int M, int Nc, int K)
{
    __shared__ float As[2][16][136];   // [k][m], stride 136 -> conflict-free frags
    __shared__ float Bs[2][16][136];   // [k][n]
    const int tid = threadIdx.x;
    const int lane = tid & 31, warp = tid >> 5;
    const int wm = (warp >> 2) * 64, wn = (warp & 3) * 32;
    const int m0 = blockIdx.y * 128, n0 = blockIdx.x * 128;
    const int g = lane >> 2, q = lane & 3;

    float acc[4][4][4];
#pragma unroll
    for (int i = 0; i < 4; i++)
#pragma unroll
        for (int j = 0; j < 4; j++)
#pragma unroll
            for (int c = 0; c < 4; c++) acc[i][j][c] = 0.f;

    // staging: each thread loads one row (srow), 8 consecutive k (skc..skc+7)
    const int srow = tid >> 1, skc = (tid & 1) * 8;
    const float* Apt = A + (size_t)(m0 + srow) * K + skc;
    const float* Wpt = W + (size_t)(n0 + srow) * K + skc;

    float4 a0 = *(const float4*)(Apt);
    float4 a1 = *(const float4*)(Apt + 4);
    float4 w0 = *(const float4*)(Wpt);
    float4 w1 = *(const float4*)(Wpt + 4);
    As[0][skc+0][srow] = t32f(a0.x); As[0][skc+1][srow] = t32f(a0.y);
    As[0][skc+2][srow] = t32f(a0.z); As[0][skc+3][srow] = t32f(a0.w);
    As[0][skc+4][srow] = t32f(a1.x); As[0][skc+5][srow] = t32f(a1.y);
    As[0][skc+6][srow] = t32f(a1.z); As[0][skc+7][srow] = t32f(a1.w);
    Bs[0][skc+0][srow] = t32f(w0.x); Bs[0][skc+1][srow] = t32f(w0.y);
    Bs[0][skc+2][srow] = t32f(w0.z); Bs[0][skc+3][srow] = t32f(w0.w);
    Bs[0][skc+4][srow] = t32f(w1.x); Bs[0][skc+5][srow] = t32f(w1.y);
    Bs[0][skc+6][srow] = t32f(w1.z); Bs[0][skc+7][srow] = t32f(w1.w);

    int buf = 0;
    for (int k0 = 16; k0 <= K; k0 += 16) {
        __syncthreads();
        const bool more = (k0 < K);
        if (more) {
            a0 = *(const float4*)(Apt + k0);
            a1 = *(const float4*)(Apt + k0 + 4);
            w0 = *(const float4*)(Wpt + k0);
            w1 = *(const float4*)(Wpt + k0 + 4);
        }
#pragma unroll
        for (int ks = 0; ks < 16; ks += 8) {
            unsigned af[4][4], bf[4][2];
#pragma unroll
            for (int mt = 0; mt < 4; mt++) {
                int mr = wm + mt * 16 + g;
                af[mt][0] = __float_as_uint(As[buf][ks + q][mr]);
                af[mt][1] = __float_as_uint(As[buf][ks + q][mr + 8]);
                af[mt][2] = __float_as_uint(As[buf][ks + 4 + q][mr]);
                af[mt][3] = __float_as_uint(As[buf][ks + 4 + q][mr + 8]);
            }
#pragma unroll
            for (int nt = 0; nt < 4; nt++) {
                int nc = wn + nt * 8 + g;
                bf[nt][0] = __float_as_uint(Bs[buf][ks + q][nc]);
                bf[nt][1] = __float_as_uint(Bs[buf][ks + 4 + q][nc]);
            }
#pragma unroll
            for (int mt = 0; mt < 4; mt++)
#pragma unroll
                for (int nt = 0; nt < 4; nt++)
                    mma8(acc[mt][nt], af[mt], bf[nt]);
        }
        if (more) {
            int nb = buf ^ 1;
            As[nb][skc+0][srow] = t32f(a0.x); As[nb][skc+1][srow] = t32f(a0.y);
            As[nb][skc+2][srow] = t32f(a0.z); As[nb][skc+3][srow] = t32f(a0.w);
            As[nb][skc+4][srow] = t32f(a1.x); As[nb][skc+5][srow] = t32f(a1.y);
            As[nb][skc+6][srow] = t32f(a1.z); As[nb][skc+7][srow] = t32f(a1.w);
            Bs[nb][skc+0][srow] = t32f(w0.x); Bs[nb][skc+1][srow] = t32f(w0.y);
            Bs[nb][skc+2][srow] = t32f(w0.z); Bs[nb][skc+3][srow] = t32f(w0.w);
            Bs[nb][skc+4][srow] = t32f(w1.x); Bs[nb][skc+5][srow] = t32f(w1.y);
            Bs[nb][skc+6][srow] = t32f(w1.z); Bs[nb][skc+7][srow] = t32f(w1.w);
        }
        buf ^= 1;
    }

#pragma unroll
    for (int mt = 0; mt < 4; mt++) {
        const int row0 = m0 + wm + mt * 16 + g;
#pragma unroll
        for (int nt = 0; nt < 4; nt++) {
            const int col = n0 + wn + nt * 8 + 2 * q;
            float v0 = acc[mt][nt][0], v1 = acc[mt][nt][1];
            float v2 = acc[mt][nt][2], v3 = acc[mt][nt][3];
            if (MODE >= 1) {
                float2 bv = *(const float2*)&bias[col];
                v0 += bv.x; v1 += bv.y; v2 += bv.x; v3 += bv.y;
            }
            if (MODE == 2) {
                v0 = 0.5f * v0 * (1.f + erff(v0 * 0.70710678118654752f));
                v1 = 0.5f * v1 * (1.f + erff(v1 * 0.70710678118654752f));
                v2 = 0.5f * v2 * (1.f + erff(v2 * 0.70710678118654752f));
                v3 = 0.5f * v3 * (1.f + erff(v3 * 0.70710678118654752f));
            }
            if (MODE == 3) {
                float2 r0 = *(const float2*)(res + (size_t)row0 * Nc + col);
                float2 r1 = *(const float2*)(res + (size_t)(row0 + 8) * Nc + col);
                v0 += r0.x; v1 += r0.y; v2 += r1.x; v3 += r1.y;
            }
            *(float2*)(C + (size_t)row0 * Nc + col)       = make_float2(v0, v1);
            *(float2*)(C + (size_t)(row0 + 8) * Nc + col) = make_float2(v2, v3);
        }
    }
}

// ================ dots: S = fused-scores(fq @ fk^T), tf32 mma, K=64 ================
__global__ void __launch_bounds__(256) dots_tc_kernel()
{
    __shared__ float As[2][16][136];
    __shared__ float Bs[2][16][136];
    const int tid = threadIdx.x;
    const int lane = tid & 31, warp = tid >> 5;
    const int wm = (warp >> 2) * 64, wn = (warp & 3) * 32;
    const int hb = blockIdx.z, h = hb >> 2, b = hb & 3;
    const int n0 = blockIdx.y * 128, m0 = blockIdx.x * 128;
    const int g = lane >> 2, q = lane & 3;

    float acc[4][4][4];
#pragma unroll
    for (int i = 0; i < 4; i++)
#pragma unroll
        for (int j = 0; j < 4; j++)
#pragma unroll
            for (int c = 0; c < 4; c++) acc[i][j][c] = 0.f;

    const float* fq = g_f;
    const float* fk = g_f + (size_t)ROWS * DIM;
    const int srow = tid >> 1, skc = (tid & 1) * 8;
    const float* Apt = fq + (size_t)(b * Nn_ + n0 + srow) * DIM + h * DH + skc;
    const float* Wpt = fk + (size_t)(b * Nn_ + m0 + srow) * DIM + h * DH + skc;

    float4 a0 = *(const float4*)(Apt);
    float4 a1 = *(const float4*)(Apt + 4);
    float4 w0 = *(const float4*)(Wpt);
    float4 w1 = *(const float4*)(Wpt + 4);
    As[0][skc+0][srow] = t32f(a0.x); As[0][skc+1][srow] = t32f(a0.y);
    As[0][skc+2][srow] = t32f(a0.z); As[0][skc+3][srow] = t32f(a0.w);
    As[0][skc+4][srow] = t32f(a1.x); As[0][skc+5][srow] = t32f(a1.y);
    As[0][skc+6][srow] = t32f(a1.z); As[0][skc+7][srow] = t32f(a1.w);
    Bs[0][skc+0][srow] = t32f(w0.x); Bs[0][skc+1][srow] = t32f(w0.y);
    Bs[0][skc+2][srow] = t32f(w0.z); Bs[0][skc+3][srow] = t32f(w0.w);
    Bs[0][skc+4][srow] = t32f(w1.x); Bs[0][skc+5][srow] = t32f(w1.y);
    Bs[0][skc+6][srow] = t32f(w1.z); Bs[0][skc+7][srow] = t32f(w1.w);

    int buf = 0;
    for (int k0 = 16; k0 <= DH; k0 += 16) {
        __syncthreads();
        const bool more = (k0 < DH);
        if (more) {
            a0 = *(const float4*)(Apt + k0);
            a1 = *(const float4*)(Apt + k0 + 4);
            w0 = *(const float4*)(Wpt + k0);
            w1 = *(const float4*)(Wpt + k0 + 4);
        }
#pragma unroll
        for (int ks = 0; ks < 16; ks += 8) {
            unsigned af[4][4], bf[4][2];
#pragma unroll
            for (int mt = 0; mt < 4; mt++) {
                int mr = wm + mt * 16 + g;
                af[mt][0] = __float_as_uint(As[buf][ks + q][mr]);
                af[mt][1] = __float_as_uint(As[buf][ks + q][mr + 8]);
                af[mt][2] = __float_as_uint(As[buf][ks + 4 + q][mr]);
                af[mt][3] = __float_as_uint(As[buf][ks + 4 + q][mr + 8]);
            }
#pragma unroll
            for (int nt = 0; nt < 4; nt++) {
                int nc = wn + nt * 8 + g;
                bf[nt][0] = __float_as_uint(Bs[buf][ks + q][nc]);
                bf[nt][1] = __float_as_uint(Bs[buf][ks + 4 + q][nc]);
            }
#pragma unroll
            for (int mt = 0; mt < 4; mt++)
#pragma unroll
                for (int nt = 0; nt < 4; nt++)
                    mma8(acc[mt][nt], af[mt], bf[nt]);
        }
        if (more) {
            int nb = buf ^ 1;
            As[nb][skc+0][srow] = t32f(a0.x); As[nb][skc+1][srow] = t32f(a0.y);
            As[nb][skc+2][srow] = t32f(a0.z); As[nb][skc+3][srow] = t32f(a0.w);
            As[nb][skc+4][srow] = t32f(a1.x); As[nb][skc+5][srow] = t32f(a1.y);
            As[nb][skc+6][srow] = t32f(a1.z); As[nb][skc+7][srow] = t32f(a1.w);
            Bs[nb][skc+0][srow] = t32f(w0.x); Bs[nb][skc+1][srow] = t32f(w0.y);
            Bs[nb][skc+2][srow] = t32f(w0.z); Bs[nb][skc+3][srow] = t32f(w0.w);
            Bs[nb][skc+4][srow] = t32f(w1.x); Bs[nb][skc+5][srow] = t32f(w1.y);
            Bs[nb][skc+6][srow] = t32f(w1.z); Bs[nb][skc+7][srow] = t32f(w1.w);
        }
        buf ^= 1;
    }

    const float cw = g_w3[h * 3 + 0], covw = g_w3[h * 3 + 1], vw = g_w3[h * 3 + 2];
    const int base = hb * Nn_;
#pragma unroll
    for (int mt = 0; mt < 4; mt++) {
        const int row0 = n0 + wm + mt * 16 + g;
        const float qi0 = g_qinv[base + row0],     qm0 = g_qmean[base + row0],     qv0 = g_qvar[base + row0];
        const float qi1 = g_qinv[base + row0 + 8], qm1 = g_qmean[base + row0 + 8], qv1 = g_qvar[base + row0 + 8];
#pragma unroll
        for (int nt = 0; nt < 4; nt++) {
            const int col = m0 + wn + nt * 8 + 2 * q;
            float2 ki = *(const float2*)&g_kinv [base + col];
            float2 km = *(const float2*)&g_kmean[base + col];
            float2 kv = *(const float2*)&g_kvar [base + col];
            float s00 = acc[mt][nt][0] * (cw * qi0 * ki.x + covw * (1.f / DH))
                      + vw * qv0 * kv.x * (1.f / DH) - covw * qm0 * km.x;
            float s01 = acc[mt][nt][1] * (cw * qi0 * ki.y + covw * (1.f / DH))
                      + vw * qv0 * kv.y * (1.f / DH) - covw * qm0 * km.y;
            float s10 = acc[mt][nt][2] * (cw * qi1 * ki.x + covw * (1.f / DH))
                      + vw * qv1 * kv.x * (1.f / DH) - covw * qm1 * km.x;
            float s11 = acc[mt][nt][3] * (cw * qi1 * ki.y + covw * (1.f / DH))
                      + vw * qv1 * kv.y * (1.f / DH) - covw * qm1 * km.y;
            *(float2*)(g_S + ((size_t)base + row0) * Nn_ + col)     = make_float2(s00, s01);
            *(float2*)(g_S + ((size_t)base + row0 + 8) * Nn_ + col) = make_float2(s10, s11);
        }
    }
}

// ================ av: O = S @ fv, tf32 mma, 128x64 tile, K=1024 ================
__global__ void __launch_bounds__(256) av_tc_kernel()
{
    __shared__ float As[2][16][136];   // [k][m]
    __shared__ float Bs[2][16][72];    // [k][n], n = d within head
    const int tid = threadIdx.x;
    const int lane = tid & 31, warp = tid >> 5;
    const int wm = (warp >> 1) * 32, wn = (warp & 1) * 32;
    const int hb = blockIdx.z, h = hb >> 2, b = hb & 3;
    const int n0 = blockIdx.y * 128;
    const int g = lane >> 2, q = lane & 3;

    float acc[2][4][4];
#pragma unroll
    for (int i = 0; i < 2; i++)
#pragma unroll
        for (int j = 0; j < 4; j++)
#pragma unroll
            for (int c = 0; c < 4; c++) acc[i][j][c] = 0.f;

    const float* fv = g_f + 2 * (size_t)ROWS * DIM;
    const int srow = tid >> 1, skc = (tid & 1) * 8;
    const float* Apt = g_S + ((size_t)hb * Nn_ + n0 + srow) * Nn_ + skc;
    const int bkr = tid >> 4, bc4 = (tid & 15) * 4;
    const float* Vpt = fv + (size_t)(b * Nn_ + bkr) * DIM + h * DH + bc4;

    float4 a0 = *(const float4*)(Apt);
    float4 a1 = *(const float4*)(Apt + 4);
    float4 vv = *(const float4*)(Vpt);
    As[0][skc+0][srow] = t32f(a0.x); As[0][skc+1][srow] = t32f(a0.y);
    As[0][skc+2][srow] = t32f(a0.z); As[0][skc+3][srow] = t32f(a0.w);
    As[0][skc+4][srow] = t32f(a1.x); As[0][skc+5][srow] = t32f(a1.y);
    As[0][skc+6][srow] = t32f(a1.z); As[0][skc+7][srow] = t32f(a1.w);
    Bs[0][bkr][bc4+0] = t32f(vv.x); Bs[0][bkr][bc4+1] = t32f(vv.y);
    Bs[0][bkr][bc4+2] = t32f(vv.z); Bs[0][bkr][bc4+3] = t32f(vv.w);

    int buf = 0;
    for (int k0 = 16; k0 <= Nn_; k0 += 16) {
        __syncthreads();
        const bool more = (k0 < Nn_);
        if (more) {
            a0 = *(const float4*)(Apt + k0);
            a1 = *(const float4*)(Apt + k0 + 4);
            vv = *(const float4*)(Vpt + (size_t)k0 * DIM);
        }
#pragma unroll
        for (int ks = 0; ks < 16; ks += 8) {
            unsigned af[2][4], bf[4][2];
#pragma unroll
            for (int mt = 0; mt < 2; mt++) {
                int mr = wm + mt * 16 + g;
                af[mt][0] = __float_as_uint(As[buf][ks + q][mr]);
                af[mt][1] = __float_as_uint(As[buf][ks + q][mr + 8]);
                af[mt][2] = __float_as_uint(As[buf][ks + 4 + q][mr]);
                af[mt][3] = __float_as_uint(As[buf][ks + 4 + q][mr + 8]);
            }
#pragma unroll
            for (int nt = 0; nt < 4; nt++) {
                int nc = wn + nt * 8 + g;
                bf[nt][0] = __float_as_uint(Bs[buf][ks + q][nc]);
                bf[nt][1] = __float_as_uint(Bs[buf][ks + 4 + q][nc]);
            }
#pragma unroll
            for (int mt = 0; mt < 2; mt++)
#pragma unroll
                for (int nt = 0; nt < 4; nt++)
                    mma8(acc[mt][nt], af[mt], bf[nt]);
        }
        if (more) {
            int nb = buf ^ 1;
            As[nb][skc+0][srow] = t32f(a0.x); As[nb][skc+1][srow] = t32f(a0.y);
            As[nb][skc+2][srow] = t32f(a0.z); As[nb][skc+3][srow] = t32f(a0.w);
            As[nb][skc+4][srow] = t32f(a1.x); As[nb][skc+5][srow] = t32f(a1.y);
            As[nb][skc+6][srow] = t32f(a1.z); As[nb][skc+7][srow] = t32f(a1.w);
            Bs[nb][bkr][bc4+0] = t32f(vv.x); Bs[nb][bkr][bc4+1] = t32f(vv.y);
            Bs[nb][bkr][bc4+2] = t32f(vv.z); Bs[nb][bkr][bc4+3] = t32f(vv.w);
        }
        buf ^= 1;
    }

#pragma unroll
    for (int mt = 0; mt < 2; mt++) {
        const int row0 = n0 + wm + mt * 16 + g;
#pragma unroll
        for (int nt = 0; nt < 4; nt++) {
            const int col = wn + nt * 8 + 2 * q;
            float* o0 = g_ao + (size_t)(b * Nn_ + row0) * DIM + h * DH + col;
            float* o1 = g_ao + (size_t)(b * Nn_ + row0 + 8) * DIM + h * DH + col;
            *(float2*)o0 = make_float2(acc[mt][nt][0], acc[mt][nt][1]);
            *(float2*)o1 = make_float2(acc[mt][nt][2], acc[mt][nt][3]);
        }
    }
}

// ---------------- per-row stats for fq, fk ----------------
__global__ void stats_kernel(const float* __restrict__ f)
{
    int w = blockIdx.x * 8 + (threadIdx.x >> 5);
    int lane = threadIdx.x & 31;
    int which = w >> 15;
    int rem = w & 32767;
    int n = rem & 1023;
    int b = (rem >> 10) & 3;
    int h = rem >> 12;
    const float* src = f + (size_t)which * ROWS * DIM
                         + ((size_t)(b * Nn_ + n)) * DIM + h * DH;
    float x0 = src[lane], x1 = src[lane + 32];
    float s = x0 + x1, ss = x0 * x0 + x1 * x1;
#pragma unroll
    for (int off = 16; off; off >>= 1) {
        s  += __shfl_xor_sync(0xffffffffu, s, off);
        ss += __shfl_xor_sync(0xffffffffu, ss, off);
    }
    if (lane == 0) {
        int idx = (h * Bq + b) * Nn_ + n;
        float mean = s * (1.f / DH);
        float var  = (ss - s * s * (1.f / DH)) * (1.f / (DH - 1));
        float inv  = rsqrtf(ss);
        if (which == 0) { g_qinv[idx] = inv; g_qmean[idx] = mean; g_qvar[idx] = var; }
        else            { g_kinv[idx] = inv; g_kmean[idx] = mean; g_kvar[idx] = var; }
    }
}

// ---------------- per-head global means ----------------
__global__ void headmean_kernel(const float* __restrict__ f)
{
    int id = blockIdx.x;
    int which = id >> 9;
    int hd = id & 511;
    const float* src = f + (size_t)which * ROWS * DIM + hd;
    float s = 0.f;
    for (int r = threadIdx.x; r < ROWS; r += 256) s += src[(size_t)r * DIM];
    __shared__ float rs[256];
    rs[threadIdx.x] = s;
    __syncthreads();
    for (int off = 128; off > 0; off >>= 1) {
        if (threadIdx.x < off) rs[threadIdx.x] += rs[threadIdx.x + off];
        __syncthreads();
    }
    if (threadIdx.x == 0) g_hg[id] = rs[0] * (1.f / ROWS);
}

// ---------------- gating MLP ----------------
__global__ void mlp_kernel(const float* __restrict__ W1, const float* __restrict__ b1,
                           const float* __restrict__ gg, const float* __restrict__ gb,
                           const float* __restrict__ W2, const float* __restrict__ b2)
{
    int h = threadIdx.x >> 5;
    int lane = threadIdx.x & 31;
    float h1[2];
#pragma unroll
    for (int t = 0; t < 2; t++) {
        int j = lane + t * 32;
        const float* wr = W1 + j * 128;
        float acc = b1[j];
        for (int i = 0; i < 64; i++) acc += g_hg[h * 64 + i] * wr[i];
        for (int i = 0; i < 64; i++) acc += g_hg[512 + h * 64 + i] * wr[64 + i];
        h1[t] = acc;
    }
    float s = h1[0] + h1[1], ss = h1[0] * h1[0] + h1[1] * h1[1];
#pragma unroll
    for (int off = 16; off; off >>= 1) {
        s  += __shfl_xor_sync(0xffffffffu, s, off);
        ss += __shfl_xor_sync(0xffffffffu, ss, off);
    }
    float mean = s * (1.f / 64.f);
    float var  = ss * (1.f / 64.f) - mean * mean;
    float inv  = rsqrtf(var + EPS);
    float hh[2];
#pragma unroll
    for (int t = 0; t < 2; t++) {
        int j = lane + t * 32;
        float v = (h1[t] - mean) * inv * gg[j] + gb[j];
        hh[t] = fmaxf(v, 0.f);
    }
    float lg[3];
#pragma unroll
    for (int c = 0; c < 3; c++) {
        float acc = hh[0] * W2[c * 64 + lane] + hh[1] * W2[c * 64 + lane + 32];
#pragma unroll
        for (int off = 16; off; off >>= 1) acc += __shfl_xor_sync(0xffffffffu, acc, off);
        lg[c] = acc + b2[c];
    }
    if (lane == 0) {
        float m = fmaxf(lg[0], fmaxf(lg[1], lg[2]));
        float e0 = expf(lg[0] - m), e1 = expf(lg[1] - m), e2 = expf(lg[2] - m);
        float inv_s = 1.f / (e0 + e1 + e2);
        g_w3[h * 3 + 0] = e0 * inv_s;
        g_w3[h * 3 + 1] = e1 * inv_s;
        g_w3[h * 3 + 2] = e2 * inv_s;
    }
}

// ---------------- launch ----------------
extern "C" void kernel_launch(void* const* d_in, const int* in_sizes, int n_in,
                              void* d_out, int out_size)
{
    const float* q    = (const float*)d_in[0];
    const float* k    = (const float*)d_in[1];
    const float* v    = (const float*)d_in[2];
    const float* Win  = (const float*)d_in[3];
    const float* Wout = (const float*)d_in[4];
    const float* bout = (const float*)d_in[5];
    const float* g1   = (const float*)d_in[6];
    const float* b1n  = (const float*)d_in[7];
    const float* g2   = (const float*)d_in[8];
    const float* b2n  = (const float*)d_in[9];
    const float* Wup  = (const float*)d_in[10];
    const float* bup  = (const float*)d_in[11];
    const float* Wdn  = (const float*)d_in[12];
    const float* bdn  = (const float*)d_in[13];
    const float* wpW1 = (const float*)d_in[14];
    const float* wpb1 = (const float*)d_in[15];
    const float* wpg  = (const float*)d_in[16];
    const float* wpb  = (const float*)d_in[17];
    const float* wpW2 = (const float*)d_in[18];
    const float* wpb2 = (const float*)d_in[19];
    float* out = (float*)d_out;

    float* xn;  cudaGetSymbolAddress((void**)&xn,  g_xn);
    float* f;   cudaGetSymbolAddress((void**)&f,   g_f);
    float* ao;  cudaGetSymbolAddress((void**)&ao,  g_ao);
    float* q2;  cudaGetSymbolAddress((void**)&q2,  g_q2);
    float* xn2; cudaGetSymbolAddress((void**)&xn2, g_xn2);
    float* u;   cudaGetSymbolAddress((void**)&u,   g_u);

    // 1. LN of q,k,v
    ln_kernel<<<ROWS, 256>>>(q, g1, b1n, xn);
    ln_kernel<<<ROWS, 256>>>(k, g1, b1n, xn + (size_t)ROWS * DIM);
    ln_kernel<<<ROWS, 256>>>(v, g1, b1n, xn + 2 * (size_t)ROWS * DIM);

    // 2. fused projection: [3*4096, 512] @ Win^T
    tmm_kernel<0><<<dim3(DIM / 128, 3 * ROWS / 128), 256>>>(xn, Win, nullptr, nullptr, f,
                                                            3 * ROWS, DIM, DIM);

    // 3. per-row stats + head means + gating MLP
    stats_kernel<<<(2 * HB * Nn_) / 8, 256>>>(f);
    headmean_kernel<<<2 * Hh * DH, 256>>>(f);
    mlp_kernel<<<1, 256>>>(wpW1, wpb1, wpg, wpb, wpW2, wpb2);

    // 4. scores (QK^T with fused 3-component epilogue)
    dots_tc_kernel<<<dim3(Nn_ / 128, Nn_ / 128, HB), 256>>>();

    // 5. O = S @ V
    av_tc_kernel<<<dim3(1, Nn_ / 128, HB), 256>>>();

    // 6. attn out proj + residual -> q2
    tmm_kernel<3><<<dim3(DIM / 128, ROWS / 128), 256>>>(ao, Wout, bout, q, q2,
                                                        ROWS, DIM, DIM);

    // 7. LN2
    ln_kernel<<<ROWS, 256>>>(q2, g2, b2n, xn2);

    // 8. MLP up + gelu
    tmm_kernel<2><<<dim3(MLPD / 128, ROWS / 128), 256>>>(xn2, Wup, bup, nullptr, u,
                                                         ROWS, MLPD, DIM);

    // 9. MLP down + residual -> out
    tmm_kernel<3><<<dim3(DIM / 128, ROWS / 128), 256>>>(u, Wdn, bdn, q2, out,
                                                        ROWS, DIM, MLPD);
}

// round 4
// speedup vs baseline: 3.0022x; 1.0199x over previous
#include <cuda_runtime.h>
#include <cuda_bf16.h>
#include <math.h>

// ---------------- problem constants ----------------
#define Bq   4
#define Nn_  1024
#define DIM  512
#define Hh   8
#define DH   64
#define MLPD 2048
#define ROWS (Bq * Nn_)            // 4096 token rows
#define HB   (Hh * Bq)             // 32 attention batches
#define EPS  1e-5f

// ---------------- tf32 mma helpers ----------------
__device__ __forceinline__ float t32f(float x){
    unsigned r; asm("cvt.rna.tf32.f32 %0,%1;" : "=r"(r) : "f"(x));
    return __uint_as_float(r);
}
__device__ __forceinline__ void mma8(float* c, const unsigned* a, const unsigned* b){
    asm("mma.sync.aligned.m16n8k8.row.col.f32.tf32.tf32.f32 "
        "{%0,%1,%2,%3},{%4,%5,%6,%7},{%8,%9},{%0,%1,%2,%3};"
        : "+f"(c[0]), "+f"(c[1]), "+f"(c[2]), "+f"(c[3])
        : "r"(a[0]), "r"(a[1]), "r"(a[2]), "r"(a[3]), "r"(b[0]), "r"(b[1]));
}

// ---------------- device scratch (no allocs allowed) ----------------
__device__ float g_xn [3 * ROWS * DIM];
__device__ float g_f  [3 * ROWS * DIM];
__device__ float g_ao [ROWS * DIM];
__device__ float g_q2 [ROWS * DIM];
__device__ float g_xn2[ROWS * DIM];
__device__ float g_u  [ROWS * MLPD];
__device__ float g_qinv [HB * Nn_];
__device__ float g_qmean[HB * Nn_];
__device__ float g_qvar [HB * Nn_];
__device__ float g_kinv [HB * Nn_];
__device__ float g_kmean[HB * Nn_];
__device__ float g_kvar [HB * Nn_];
__device__ float g_hg [2 * Hh * DH];
__device__ float g_w3 [Hh * 3];

// ---------------- layernorm over rows of 512 ----------------
__global__ void ln_kernel(const float* __restrict__ x, const float* __restrict__ g,
                          const float* __restrict__ bb, float* __restrict__ y)
{
    int row = blockIdx.x;
    int tid = threadIdx.x;
    const float* xr = x + (size_t)row * DIM;
    float v0 = xr[tid], v1 = xr[tid + 256];
    float s = v0 + v1, ss = v0 * v0 + v1 * v1;
    __shared__ float rs[256], rss[256];
    rs[tid] = s; rss[tid] = ss;
    __syncthreads();
    for (int off = 128; off > 0; off >>= 1) {
        if (tid < off) { rs[tid] += rs[tid + off]; rss[tid] += rss[tid + off]; }
        __syncthreads();
    }
    float mean = rs[0] * (1.f / DIM);
    float var  = rss[0] * (1.f / DIM) - mean * mean;
    float inv  = rsqrtf(var + EPS);
    float* yr = y + (size_t)row * DIM;
    yr[tid]       = (v0 - mean) * inv * g[tid]       + bb[tid];
    yr[tid + 256] = (v1 - mean) * inv * g[tid + 256] + bb[tid + 256];
}

// ================ tf32 tensor-core GEMM: C = A[M,K] @ W[N,K]^T ================
// 128x128 CTA tile, BK=16, 8 warps each 64x32.
// MODE: 0 plain, 1 +bias, 2 +bias+gelu(exact), 3 +bias+residual, 4 plain+tf32-round
template <int MODE>
__global__ void __launch_bounds__(256) tmm_kernel(
    const float* __restrict__ A, const float* __restrict__ W,
    const float* __restrict__ bias, const float* __restrict__ res,
    float* __restrict__ C, int M, int Nc, int K)
{
    __shared__ float As[2][16][136];   // [k][m]
    __shared__ float Bs[2][16][136];   // [k][n]
    const int tid = threadIdx.x;
    const int lane = tid & 31, warp = tid >> 5;
    const int wm = (warp >> 2) * 64, wn = (warp & 3) * 32;
    const int m0 = blockIdx.y * 128, n0 = blockIdx.x * 128;
    const int g = lane >> 2, q = lane & 3;

    float acc[4][4][4];
#pragma unroll
    for (int i = 0; i < 4; i++)
#pragma unroll
        for (int j = 0; j < 4; j++)
#pragma unroll
            for (int c = 0; c < 4; c++) acc[i][j][c] = 0.f;

    const int srow = tid >> 1, skc = (tid & 1) * 8;
    const float* Apt = A + (size_t)(m0 + srow) * K + skc;
    const float* Wpt = W + (size_t)(n0 + srow) * K + skc;

    float4 a0 = *(const float4*)(Apt);
    float4 a1 = *(const float4*)(Apt + 4);
    float4 w0 = *(const float4*)(Wpt);
    float4 w1 = *(const float4*)(Wpt + 4);
    As[0][skc+0][srow] = t32f(a0.x); As[0][skc+1][srow] = t32f(a0.y);
    As[0][skc+2][srow] = t32f(a0.z); As[0][skc+3][srow] = t32f(a0.w);
    As[0][skc+4][srow] = t32f(a1.x); As[0][skc+5][srow] = t32f(a1.y);
    As[0][skc+6][srow] = t32f(a1.z); As[0][skc+7][srow] = t32f(a1.w);
    Bs[0][skc+0][srow] = t32f(w0.x); Bs[0][skc+1][srow] = t32f(w0.y);
    Bs[0][skc+2][srow] = t32f(w0.z); Bs[0][skc+3][srow] = t32f(w0.w);
    Bs[0][skc+4][srow] = t32f(w1.x); Bs[0][skc+5][srow] = t32f(w1.y);
    Bs[0][skc+6][srow] = t32f(w1.z); Bs[0][skc+7][srow] = t32f(w1.w);

    int buf = 0;
    for (int k0 = 16; k0 <= K; k0 += 16) {
        __syncthreads();
        const bool more = (k0 < K);
        if (more) {
            a0 = *(const float4*)(Apt + k0);
            a1 = *(const float4*)(Apt + k0 + 4);
            w0 = *(const float4*)(Wpt + k0);
            w1 = *(const float4*)(Wpt + k0 + 4);
        }
#pragma unroll
        for (int ks = 0; ks < 16; ks += 8) {
            unsigned af[4][4], bf[4][2];
#pragma unroll
            for (int mt = 0; mt < 4; mt++) {
                int mr = wm + mt * 16 + g;
                af[mt][0] = __float_as_uint(As[buf][ks + q][mr]);
                af[mt][1] = __float_as_uint(As[buf][ks + q][mr + 8]);
                af[mt][2] = __float_as_uint(As[buf][ks + 4 + q][mr]);
                af[mt][3] = __float_as_uint(As[buf][ks + 4 + q][mr + 8]);
            }
#pragma unroll
            for (int nt = 0; nt < 4; nt++) {
                int nc = wn + nt * 8 + g;
                bf[nt][0] = __float_as_uint(Bs[buf][ks + q][nc]);
                bf[nt][1] = __float_as_uint(Bs[buf][ks + 4 + q][nc]);
            }
#pragma unroll
            for (int mt = 0; mt < 4; mt++)
#pragma unroll
                for (int nt = 0; nt < 4; nt++)
                    mma8(acc[mt][nt], af[mt], bf[nt]);
        }
        if (more) {
            int nb = buf ^ 1;
            As[nb][skc+0][srow] = t32f(a0.x); As[nb][skc+1][srow] = t32f(a0.y);
            As[nb][skc+2][srow] = t32f(a0.z); As[nb][skc+3][srow] = t32f(a0.w);
            As[nb][skc+4][srow] = t32f(a1.x); As[nb][skc+5][srow] = t32f(a1.y);
            As[nb][skc+6][srow] = t32f(a1.z); As[nb][skc+7][srow] = t32f(a1.w);
            Bs[nb][skc+0][srow] = t32f(w0.x); Bs[nb][skc+1][srow] = t32f(w0.y);
            Bs[nb][skc+2][srow] = t32f(w0.z); Bs[nb][skc+3][srow] = t32f(w0.w);
            Bs[nb][skc+4][srow] = t32f(w1.x); Bs[nb][skc+5][srow] = t32f(w1.y);
            Bs[nb][skc+6][srow] = t32f(w1.z); Bs[nb][skc+7][srow] = t32f(w1.w);
        }
        buf ^= 1;
    }

#pragma unroll
    for (int mt = 0; mt < 4; mt++) {
        const int row0 = m0 + wm + mt * 16 + g;
#pragma unroll
        for (int nt = 0; nt < 4; nt++) {
            const int col = n0 + wn + nt * 8 + 2 * q;
            float v0 = acc[mt][nt][0], v1 = acc[mt][nt][1];
            float v2 = acc[mt][nt][2], v3 = acc[mt][nt][3];
            if (MODE == 1 || MODE == 2 || MODE == 3) {
                float2 bv = *(const float2*)&bias[col];
                v0 += bv.x; v1 += bv.y; v2 += bv.x; v3 += bv.y;
            }
            if (MODE == 2) {
                v0 = 0.5f * v0 * (1.f + erff(v0 * 0.70710678118654752f));
                v1 = 0.5f * v1 * (1.f + erff(v1 * 0.70710678118654752f));
                v2 = 0.5f * v2 * (1.f + erff(v2 * 0.70710678118654752f));
                v3 = 0.5f * v3 * (1.f + erff(v3 * 0.70710678118654752f));
            }
            if (MODE == 3) {
                float2 r0 = *(const float2*)(res + (size_t)row0 * Nc + col);
                float2 r1 = *(const float2*)(res + (size_t)(row0 + 8) * Nc + col);
                v0 += r0.x; v1 += r0.y; v2 += r1.x; v3 += r1.y;
            }
            if (MODE == 4) {
                v0 = t32f(v0); v1 = t32f(v1); v2 = t32f(v2); v3 = t32f(v3);
            }
            *(float2*)(C + (size_t)row0 * Nc + col)       = make_float2(v0, v1);
            *(float2*)(C + (size_t)(row0 + 8) * Nc + col) = make_float2(v2, v3);
        }
    }
}

// ================ fused attention: O = scores(fq,fk) @ fv ================
// grid (8 q-tiles, 32 hb), 256 threads (8 warps, warp = 16 q-rows).
// Per key-tile of 128: S-tile via mma (K=64), epilogue in regs, repack S into
// A-fragment layout in warp-private smem, mma against V-tile, accumulate O.
// smem: Bs[64][136] fk ([d][key]) | Vs[128][72] fv ([key][d]) | Qs/Ss union.
#define ATTN_SMEM_FLOATS (64*136 + 128*72 + 16384)

__global__ void __launch_bounds__(256) attn_fused_kernel()
{
    extern __shared__ float sm[];
    float* Bsm = sm;                       // 8704 floats
    float* Vsm = sm + 64 * 136;            // 9216 floats
    float* Qsm = sm + 64 * 136 + 128 * 72; // 8704 used for fq stage; then Ss (16384)
    float* Ssm = Qsm;

    const int tid = threadIdx.x, lane = tid & 31, warp = tid >> 5;
    const int g = lane >> 2, q4 = lane & 3;
    const int hb = blockIdx.y, h = hb >> 2, b = hb & 3;
    const int q0 = blockIdx.x * 128;
    const int base = hb * Nn_;

    const float* fq = g_f;
    const float* fk = g_f + (size_t)ROWS * DIM;
    const float* fv = g_f + 2 * (size_t)ROWS * DIM;

    // ---- stage fq tile (already tf32-rounded) into Qsm [d][m] ----
    {
        const int row = tid & 127, d0 = (tid >> 7) * 32;
        const float* src = fq + (size_t)(b * Nn_ + q0 + row) * DIM + h * DH + d0;
#pragma unroll
        for (int i = 0; i < 8; i++) {
            float4 t = *(const float4*)(src + 4 * i);
            Qsm[(d0 + 4*i + 0) * 136 + row] = t.x;
            Qsm[(d0 + 4*i + 1) * 136 + row] = t.y;
            Qsm[(d0 + 4*i + 2) * 136 + row] = t.z;
            Qsm[(d0 + 4*i + 3) * 136 + row] = t.w;
        }
    }
    __syncthreads();

    // ---- per-warp fq A-fragments in registers (reused for all key tiles) ----
    unsigned afq[8][4];
    {
        const int mr = warp * 16 + g;
#pragma unroll
        for (int c = 0; c < 8; c++) {
            afq[c][0] = __float_as_uint(Qsm[(8*c + q4) * 136 + mr]);
            afq[c][1] = __float_as_uint(Qsm[(8*c + q4) * 136 + mr + 8]);
            afq[c][2] = __float_as_uint(Qsm[(8*c + 4 + q4) * 136 + mr]);
            afq[c][3] = __float_as_uint(Qsm[(8*c + 4 + q4) * 136 + mr + 8]);
        }
    }
    // q-row stats for this thread's two rows
    const int qr = q0 + warp * 16 + g;
    const float qi0 = g_qinv[base + qr],     qm0 = g_qmean[base + qr],     qv0 = g_qvar[base + qr];
    const float qi1 = g_qinv[base + qr + 8], qm1 = g_qmean[base + qr + 8], qv1 = g_qvar[base + qr + 8];
    const float cw = g_w3[h * 3 + 0], covw = g_w3[h * 3 + 1], vw = g_w3[h * 3 + 2];

    float accO[8][4];
#pragma unroll
    for (int j = 0; j < 8; j++)
#pragma unroll
        for (int c = 0; c < 4; c++) accO[j][c] = 0.f;

    __syncthreads();   // all fq frag loads done before Ssm writes

    const int sgr = lane ^ ((lane >> 3) << 1);   // read-side swizzled group

    for (int kt = 0; kt < 8; kt++) {
        const int k0 = kt * 128;
        // ---- stage fk -> Bsm [d][key], fv -> Vsm [key][d] (data already tf32) ----
        {
            const int key = tid & 127, d0 = (tid >> 7) * 32;
            const float* sk = fk + (size_t)(b * Nn_ + k0 + key) * DIM + h * DH + d0;
            const float* sv = fv + (size_t)(b * Nn_ + k0 + key) * DIM + h * DH + d0;
#pragma unroll
            for (int i = 0; i < 8; i++) {
                float4 t = *(const float4*)(sk + 4 * i);
                Bsm[(d0 + 4*i + 0) * 136 + key] = t.x;
                Bsm[(d0 + 4*i + 1) * 136 + key] = t.y;
                Bsm[(d0 + 4*i + 2) * 136 + key] = t.z;
                Bsm[(d0 + 4*i + 3) * 136 + key] = t.w;
            }
#pragma unroll
            for (int i = 0; i < 8; i++) {
                float4 t = *(const float4*)(sv + 4 * i);
                *(float4*)&Vsm[key * 72 + d0 + 4 * i] = t;
            }
        }
        __syncthreads();

        // ---- S-tile: accS[16 n8-tiles][4] = fq(16 rows) @ fk(128 keys)^T ----
        float accS[16][4];
#pragma unroll
        for (int j = 0; j < 16; j++)
#pragma unroll
            for (int c = 0; c < 4; c++) accS[j][c] = 0.f;
#pragma unroll
        for (int c = 0; c < 8; c++) {
#pragma unroll
            for (int nt = 0; nt < 16; nt++) {
                unsigned bf[2];
                bf[0] = __float_as_uint(Bsm[(8*c + q4) * 136 + nt * 8 + g]);
                bf[1] = __float_as_uint(Bsm[(8*c + 4 + q4) * 136 + nt * 8 + g]);
                mma8(accS[nt], afq[c], bf);
            }
        }

        // ---- epilogue + repack S into A-fragment layout (warp-private) ----
        float* sw = Ssm + warp * 2048;
        {
            const int l0 = 4 * g + 2 * (q4 & 1);
            const int r0 = 2 * (q4 >> 1);
            const int sg0 = l0 ^ ((l0 >> 3) << 1);
            const int l1 = l0 + 1;
            const int sg1 = l1 ^ ((l1 >> 3) << 1);
#pragma unroll
            for (int nt = 0; nt < 16; nt++) {
                const int col = k0 + nt * 8 + 2 * q4;
                float2 ki = *(const float2*)&g_kinv [base + col];
                float2 km = *(const float2*)&g_kmean[base + col];
                float2 kv = *(const float2*)&g_kvar [base + col];
                float s00 = accS[nt][0] * (cw * qi0 * ki.x + covw * (1.f / DH))
                          + vw * qv0 * kv.x * (1.f / DH) - covw * qm0 * km.x;
                float s01 = accS[nt][1] * (cw * qi0 * ki.y + covw * (1.f / DH))
                          + vw * qv0 * kv.y * (1.f / DH) - covw * qm0 * km.y;
                float s10 = accS[nt][2] * (cw * qi1 * ki.x + covw * (1.f / DH))
                          + vw * qv1 * kv.x * (1.f / DH) - covw * qm1 * km.x;
                float s11 = accS[nt][3] * (cw * qi1 * ki.y + covw * (1.f / DH))
                          + vw * qv1 * kv.y * (1.f / DH) - covw * qm1 * km.y;
                float* cb = sw + nt * 128;
                cb[sg0 * 4 + r0]     = t32f(s00);
                cb[sg1 * 4 + r0]     = t32f(s01);
                cb[sg0 * 4 + r0 + 1] = t32f(s10);
                cb[sg1 * 4 + r0 + 1] = t32f(s11);
            }
        }
        __syncwarp();

        // ---- O-mma: accO += S(16 x 128keys) @ V(128keys x 64d) ----
#pragma unroll
        for (int c = 0; c < 16; c++) {
            float4 a4 = *(const float4*)(sw + c * 128 + sgr * 4);
            unsigned as[4];
            as[0] = __float_as_uint(a4.x); as[1] = __float_as_uint(a4.y);
            as[2] = __float_as_uint(a4.z); as[3] = __float_as_uint(a4.w);
#pragma unroll
            for (int nt = 0; nt < 8; nt++) {
                unsigned bf[2];
                bf[0] = __float_as_uint(Vsm[(8*c + q4) * 72 + nt * 8 + g]);
                bf[1] = __float_as_uint(Vsm[(8*c + 4 + q4) * 72 + nt * 8 + g]);
                mma8(accO[nt], as, bf);
            }
        }
        __syncthreads();   // Bsm/Vsm free for next tile
    }

    // ---- write O ----
#pragma unroll
    for (int nt = 0; nt < 8; nt++) {
        const int col = nt * 8 + 2 * q4;
        float* o0 = g_ao + (size_t)(b * Nn_ + qr) * DIM + h * DH + col;
        float* o1 = g_ao + (size_t)(b * Nn_ + qr + 8) * DIM + h * DH + col;
        *(float2*)o0 = make_float2(accO[nt][0], accO[nt][1]);
        *(float2*)o1 = make_float2(accO[nt][2], accO[nt][3]);
    }
}

// ---------------- per-row stats for fq, fk ----------------
__global__ void stats_kernel(const float* __restrict__ f)
{
    int w = blockIdx.x * 8 + (threadIdx.x >> 5);
    int lane = threadIdx.x & 31;
    int which = w >> 15;
    int rem = w & 32767;
    int n = rem & 1023;
    int b = (rem >> 10) & 3;
    int h = rem >> 12;
    const float* src = f + (size_t)which * ROWS * DIM
                         + ((size_t)(b * Nn_ + n)) * DIM + h * DH;
    float x0 = src[lane], x1 = src[lane + 32];
    float s = x0 + x1, ss = x0 * x0 + x1 * x1;
#pragma unroll
    for (int off = 16; off; off >>= 1) {
        s  += __shfl_xor_sync(0xffffffffu, s, off);
        ss += __shfl_xor_sync(0xffffffffu, ss, off);
    }
    if (lane == 0) {
        int idx = (h * Bq + b) * Nn_ + n;
        float mean = s * (1.f / DH);
        float var  = (ss - s * s * (1.f / DH)) * (1.f / (DH - 1));
        float inv  = rsqrtf(ss);
        if (which == 0) { g_qinv[idx] = inv; g_qmean[idx] = mean; g_qvar[idx] = var; }
        else            { g_kinv[idx] = inv; g_kmean[idx] = mean; g_kvar[idx] = var; }
    }
}

// ---------------- per-head global means ----------------
__global__ void headmean_kernel(const float* __restrict__ f)
{
    int id = blockIdx.x;
    int which = id >> 9;
    int hd = id & 511;
    const float* src = f + (size_t)which * ROWS * DIM + hd;
    float s = 0.f;
    for (int r = threadIdx.x; r < ROWS; r += 256) s += src[(size_t)r * DIM];
    __shared__ float rs[256];
    rs[threadIdx.x] = s;
    __syncthreads();
    for (int off = 128; off > 0; off >>= 1) {
        if (threadIdx.x < off) rs[threadIdx.x] += rs[threadIdx.x + off];
        __syncthreads();
    }
    if (threadIdx.x == 0) g_hg[id] = rs[0] * (1.f / ROWS);
}

// ---------------- gating MLP ----------------
__global__ void mlp_kernel(const float* __restrict__ W1, const float* __restrict__ b1,
                           const float* __restrict__ gg, const float* __restrict__ gb,
                           const float* __restrict__ W2, const float* __restrict__ b2)
{
    int h = threadIdx.x >> 5;
    int lane = threadIdx.x & 31;
    float h1[2];
#pragma unroll
    for (int t = 0; t < 2; t++) {
        int j = lane + t * 32;
        const float* wr = W1 + j * 128;
        float acc = b1[j];
        for (int i = 0; i < 64; i++) acc += g_hg[h * 64 + i] * wr[i];
        for (int i = 0; i < 64; i++) acc += g_hg[512 + h * 64 + i] * wr[64 + i];
        h1[t] = acc;
    }
    float s = h1[0] + h1[1], ss = h1[0] * h1[0] + h1[1] * h1[1];
#pragma unroll
    for (int off = 16; off; off >>= 1) {
        s  += __shfl_xor_sync(0xffffffffu, s, off);
        ss += __shfl_xor_sync(0xffffffffu, ss, off);
    }
    float mean = s * (1.f / 64.f);
    float var  = ss * (1.f / 64.f) - mean * mean;
    float inv  = rsqrtf(var + EPS);
    float hh[2];
#pragma unroll
    for (int t = 0; t < 2; t++) {
        int j = lane + t * 32;
        float v = (h1[t] - mean) * inv * gg[j] + gb[j];
        hh[t] = fmaxf(v, 0.f);
    }
    float lg[3];
#pragma unroll
    for (int c = 0; c < 3; c++) {
        float acc = hh[0] * W2[c * 64 + lane] + hh[1] * W2[c * 64 + lane + 32];
#pragma unroll
        for (int off = 16; off; off >>= 1) acc += __shfl_xor_sync(0xffffffffu, acc, off);
        lg[c] = acc + b2[c];
    }
    if (lane == 0) {
        float m = fmaxf(lg[0], fmaxf(lg[1], lg[2]));
        float e0 = expf(lg[0] - m), e1 = expf(lg[1] - m), e2 = expf(lg[2] - m);
        float inv_s = 1.f / (e0 + e1 + e2);
        g_w3[h * 3 + 0] = e0 * inv_s;
        g_w3[h * 3 + 1] = e1 * inv_s;
        g_w3[h * 3 + 2] = e2 * inv_s;
    }
}

// ---------------- launch ----------------
extern "C" void kernel_launch(void* const* d_in, const int* in_sizes, int n_in,
                              void* d_out, int out_size)
{
    const float* q    = (const float*)d_in[0];
    const float* k    = (const float*)d_in[1];
    const float* v    = (const float*)d_in[2];
    const float* Win  = (const float*)d_in[3];
    const float* Wout = (const float*)d_in[4];
    const float* bout = (const float*)d_in[5];
    const float* g1   = (const float*)d_in[6];
    const float* b1n  = (const float*)d_in[7];
    const float* g2   = (const float*)d_in[8];
    const float* b2n  = (const float*)d_in[9];
    const float* Wup  = (const float*)d_in[10];
    const float* bup  = (const float*)d_in[11];
    const float* Wdn  = (const float*)d_in[12];
    const float* bdn  = (const float*)d_in[13];
    const float* wpW1 = (const float*)d_in[14];
    const float* wpb1 = (const float*)d_in[15];
    const float* wpg  = (const float*)d_in[16];
    const float* wpb  = (const float*)d_in[17];
    const float* wpW2 = (const float*)d_in[18];
    const float* wpb2 = (const float*)d_in[19];
    float* out = (float*)d_out;

    float* xn;  cudaGetSymbolAddress((void**)&xn,  g_xn);
    float* f;   cudaGetSymbolAddress((void**)&f,   g_f);
    float* ao;  cudaGetSymbolAddress((void**)&ao,  g_ao);
    float* q2;  cudaGetSymbolAddress((void**)&q2,  g_q2);
    float* xn2; cudaGetSymbolAddress((void**)&xn2, g_xn2);
    float* u;   cudaGetSymbolAddress((void**)&u,   g_u);

    const int attn_smem = ATTN_SMEM_FLOATS * 4;
    cudaFuncSetAttribute(attn_fused_kernel,
                         cudaFuncAttributeMaxDynamicSharedMemorySize, attn_smem);

    // 1. LN of q,k,v
    ln_kernel<<<ROWS, 256>>>(q, g1, b1n, xn);
    ln_kernel<<<ROWS, 256>>>(k, g1, b1n, xn + (size_t)ROWS * DIM);
    ln_kernel<<<ROWS, 256>>>(v, g1, b1n, xn + 2 * (size_t)ROWS * DIM);

    // 2. fused projection (output rounded to tf32)
    tmm_kernel<4><<<dim3(DIM / 128, 3 * ROWS / 128), 256>>>(xn, Win, nullptr, nullptr, f,
                                                            3 * ROWS, DIM, DIM);

    // 3. per-row stats + head means + gating MLP
    stats_kernel<<<(2 * HB * Nn_) / 8, 256>>>(f);
    headmean_kernel<<<2 * Hh * DH, 256>>>(f);
    mlp_kernel<<<1, 256>>>(wpW1, wpb1, wpg, wpb, wpW2, wpb2);

    // 4. fused attention (scores + O in one kernel, no S round-trip)
    attn_fused_kernel<<<dim3(Nn_ / 128, HB), 256, attn_smem>>>();

    // 5. attn out proj + residual -> q2
    tmm_kernel<3><<<dim3(DIM / 128, ROWS / 128), 256>>>(ao, Wout, bout, q, q2,
                                                        ROWS, DIM, DIM);

    // 6. LN2
    ln_kernel<<<ROWS, 256>>>(q2, g2, b2n, xn2);

    // 7. MLP up + gelu
    tmm_kernel<2><<<dim3(MLPD / 128, ROWS / 128), 256>>>(xn2, Wup, bup, nullptr, u,
                                                         ROWS, MLPD, DIM);

    // 8. MLP down + residual -> out
    tmm_kernel<3><<<dim3(DIM / 128, ROWS / 128), 256>>>(u, Wdn, bdn, q2, out,
                                                        ROWS, DIM, MLPD);
}

// round 5
// speedup vs baseline: 3.6264x; 1.2079x over previous
#include <cuda_runtime.h>
#include <cuda_bf16.h>
#include <math.h>

// ---------------- problem constants ----------------
#define Bq   4
#define Nn_  1024
#define DIM  512
#define Hh   8
#define DH   64
#define MLPD 2048
#define ROWS (Bq * Nn_)            // 4096 token rows
#define HB   (Hh * Bq)             // 32 attention batches
#define EPS  1e-5f
#define MST  80                    // g_M row stride (floats)
#define KSPLIT 4

// ---------------- tf32 mma helpers ----------------
__device__ __forceinline__ float t32f(float x){
    unsigned r; asm("cvt.rna.tf32.f32 %0,%1;" : "=r"(r) : "f"(x));
    return __uint_as_float(r);
}
__device__ __forceinline__ void mma8(float* c, const unsigned* a, const unsigned* b){
    asm("mma.sync.aligned.m16n8k8.row.col.f32.tf32.tf32.f32 "
        "{%0,%1,%2,%3},{%4,%5,%6,%7},{%8,%9},{%0,%1,%2,%3};"
        : "+f"(c[0]), "+f"(c[1]), "+f"(c[2]), "+f"(c[3])
        : "r"(a[0]), "r"(a[1]), "r"(a[2]), "r"(a[3]), "r"(b[0]), "r"(b[1]));
}

// ---------------- device scratch (no allocs allowed) ----------------
__device__ float g_xn [3 * ROWS * DIM];
__device__ float g_f  [3 * ROWS * DIM];
__device__ float g_ao [ROWS * DIM];
__device__ float g_q2 [ROWS * DIM];
__device__ float g_xn2[ROWS * DIM];
__device__ float g_u  [ROWS * MLPD];
__device__ float g_Mp [KSPLIT][HB][128][MST];   // split-K partials of Mcat
__device__ float g_Mr [HB][128][MST];           // reduced Mcat (row d', col e)
__device__ float g_qinv [HB * Nn_];
__device__ float g_qmean[HB * Nn_];
__device__ float g_qvar [HB * Nn_];
__device__ float g_kinv [HB * Nn_];
__device__ float g_kmean[HB * Nn_];
__device__ float g_kvar [HB * Nn_];
__device__ float g_hg [2 * Hh * DH];
__device__ float g_w3 [Hh * 3];

// ---------------- layernorm over rows of 512 ----------------
__global__ void ln_kernel(const float* __restrict__ x, const float* __restrict__ g,
                          const float* __restrict__ bb, float* __restrict__ y)
{
    int row = blockIdx.x;
    int tid = threadIdx.x;
    const float* xr = x + (size_t)row * DIM;
    float v0 = xr[tid], v1 = xr[tid + 256];
    float s = v0 + v1, ss = v0 * v0 + v1 * v1;
    __shared__ float rs[256], rss[256];
    rs[tid] = s; rss[tid] = ss;
    __syncthreads();
    for (int off = 128; off > 0; off >>= 1) {
        if (tid < off) { rs[tid] += rs[tid + off]; rss[tid] += rss[tid + off]; }
        __syncthreads();
    }
    float mean = rs[0] * (1.f / DIM);
    float var  = rss[0] * (1.f / DIM) - mean * mean;
    float inv  = rsqrtf(var + EPS);
    float* yr = y + (size_t)row * DIM;
    yr[tid]       = (v0 - mean) * inv * g[tid]       + bb[tid];
    yr[tid + 256] = (v1 - mean) * inv * g[tid + 256] + bb[tid + 256];
}

// ================ tf32 tensor-core GEMM: C = A[M,K] @ W[N,K]^T ================
// MODE: 0 plain, 1 +bias, 2 +bias+gelu, 3 +bias+residual, 4 plain+tf32-round
template <int MODE>
__global__ void __launch_bounds__(256) tmm_kernel(
    const float* __restrict__ A, const float* __restrict__ W,
    const float* __restrict__ bias, const float* __restrict__ res,
    float* __restrict__ C, int M, int Nc, int K)
{
    __shared__ float As[2][16][136];
    __shared__ float Bs[2][16][136];
    const int tid = threadIdx.x;
    const int lane = tid & 31, warp = tid >> 5;
    const int wm = (warp >> 2) * 64, wn = (warp & 3) * 32;
    const int m0 = blockIdx.y * 128, n0 = blockIdx.x * 128;
    const int g = lane >> 2, q = lane & 3;

    float acc[4][4][4];
#pragma unroll
    for (int i = 0; i < 4; i++)
#pragma unroll
        for (int j = 0; j < 4; j++)
#pragma unroll
            for (int c = 0; c < 4; c++) acc[i][j][c] = 0.f;

    const int srow = tid >> 1, skc = (tid & 1) * 8;
    const float* Apt = A + (size_t)(m0 + srow) * K + skc;
    const float* Wpt = W + (size_t)(n0 + srow) * K + skc;

    float4 a0 = *(const float4*)(Apt);
    float4 a1 = *(const float4*)(Apt + 4);
    float4 w0 = *(const float4*)(Wpt);
    float4 w1 = *(const float4*)(Wpt + 4);
    As[0][skc+0][srow] = t32f(a0.x); As[0][skc+1][srow] = t32f(a0.y);
    As[0][skc+2][srow] = t32f(a0.z); As[0][skc+3][srow] = t32f(a0.w);
    As[0][skc+4][srow] = t32f(a1.x); As[0][skc+5][srow] = t32f(a1.y);
    As[0][skc+6][srow] = t32f(a1.z); As[0][skc+7][srow] = t32f(a1.w);
    Bs[0][skc+0][srow] = t32f(w0.x); Bs[0][skc+1][srow] = t32f(w0.y);
    Bs[0][skc+2][srow] = t32f(w0.z); Bs[0][skc+3][srow] = t32f(w0.w);
    Bs[0][skc+4][srow] = t32f(w1.x); Bs[0][skc+5][srow] = t32f(w1.y);
    Bs[0][skc+6][srow] = t32f(w1.z); Bs[0][skc+7][srow] = t32f(w1.w);

    int buf = 0;
    for (int k0 = 16; k0 <= K; k0 += 16) {
        __syncthreads();
        const bool more = (k0 < K);
        if (more) {
            a0 = *(const float4*)(Apt + k0);
            a1 = *(const float4*)(Apt + k0 + 4);
            w0 = *(const float4*)(Wpt + k0);
            w1 = *(const float4*)(Wpt + k0 + 4);
        }
#pragma unroll
        for (int ks = 0; ks < 16; ks += 8) {
            unsigned af[4][4], bf[4][2];
#pragma unroll
            for (int mt = 0; mt < 4; mt++) {
                int mr = wm + mt * 16 + g;
                af[mt][0] = __float_as_uint(As[buf][ks + q][mr]);
                af[mt][1] = __float_as_uint(As[buf][ks + q][mr + 8]);
                af[mt][2] = __float_as_uint(As[buf][ks + 4 + q][mr]);
                af[mt][3] = __float_as_uint(As[buf][ks + 4 + q][mr + 8]);
            }
#pragma unroll
            for (int nt = 0; nt < 4; nt++) {
                int nc = wn + nt * 8 + g;
                bf[nt][0] = __float_as_uint(Bs[buf][ks + q][nc]);
                bf[nt][1] = __float_as_uint(Bs[buf][ks + 4 + q][nc]);
            }
#pragma unroll
            for (int mt = 0; mt < 4; mt++)
#pragma unroll
                for (int nt = 0; nt < 4; nt++)
                    mma8(acc[mt][nt], af[mt], bf[nt]);
        }
        if (more) {
            int nb = buf ^ 1;
            As[nb][skc+0][srow] = t32f(a0.x); As[nb][skc+1][srow] = t32f(a0.y);
            As[nb][skc+2][srow] = t32f(a0.z); As[nb][skc+3][srow] = t32f(a0.w);
            As[nb][skc+4][srow] = t32f(a1.x); As[nb][skc+5][srow] = t32f(a1.y);
            As[nb][skc+6][srow] = t32f(a1.z); As[nb][skc+7][srow] = t32f(a1.w);
            Bs[nb][skc+0][srow] = t32f(w0.x); Bs[nb][skc+1][srow] = t32f(w0.y);
            Bs[nb][skc+2][srow] = t32f(w0.z); Bs[nb][skc+3][srow] = t32f(w0.w);
            Bs[nb][skc+4][srow] = t32f(w1.x); Bs[nb][skc+5][srow] = t32f(w1.y);
            Bs[nb][skc+6][srow] = t32f(w1.z); Bs[nb][skc+7][srow] = t32f(w1.w);
        }
        buf ^= 1;
    }

#pragma unroll
    for (int mt = 0; mt < 4; mt++) {
        const int row0 = m0 + wm + mt * 16 + g;
#pragma unroll
        for (int nt = 0; nt < 4; nt++) {
            const int col = n0 + wn + nt * 8 + 2 * q;
            float v0 = acc[mt][nt][0], v1 = acc[mt][nt][1];
            float v2 = acc[mt][nt][2], v3 = acc[mt][nt][3];
            if (MODE == 1 || MODE == 2 || MODE == 3) {
                float2 bv = *(const float2*)&bias[col];
                v0 += bv.x; v1 += bv.y; v2 += bv.x; v3 += bv.y;
            }
            if (MODE == 2) {
                v0 = 0.5f * v0 * (1.f + erff(v0 * 0.70710678118654752f));
                v1 = 0.5f * v1 * (1.f + erff(v1 * 0.70710678118654752f));
                v2 = 0.5f * v2 * (1.f + erff(v2 * 0.70710678118654752f));
                v3 = 0.5f * v3 * (1.f + erff(v3 * 0.70710678118654752f));
            }
            if (MODE == 3) {
                float2 r0 = *(const float2*)(res + (size_t)row0 * Nc + col);
                float2 r1 = *(const float2*)(res + (size_t)(row0 + 8) * Nc + col);
                v0 += r0.x; v1 += r0.y; v2 += r1.x; v3 += r1.y;
            }
            if (MODE == 4) {
                v0 = t32f(v0); v1 = t32f(v1); v2 = t32f(v2); v3 = t32f(v3);
            }
            *(float2*)(C + (size_t)row0 * Nc + col)       = make_float2(v0, v1);
            *(float2*)(C + (size_t)(row0 + 8) * Nc + col) = make_float2(v2, v3);
        }
    }
}

// ================ mbuild: Mcat[d'=128][e=72] = Vx^T @ Ax per hb (split-K) ======
// Vx[m, 2d] = V[m,d], Vx[m, 2d+1] = ki[m]*V[m,d]
// Ax[m, e<64] = fk[m,e], Ax[m,64] = kv[m], Ax[m,65] = km[m], else 0
__global__ void __launch_bounds__(256) mbuild_kernel()
{
    __shared__ float As[2][16][136];   // [m-chunk][d' 0..127]
    __shared__ float Bs[2][16][72];    // [m-chunk][e 0..71]
    const int tid = threadIdx.x, lane = tid & 31, warp = tid >> 5;
    const int ks = blockIdx.x, hb = blockIdx.y, h = hb >> 2, b = hb & 3;
    const int base = hb * Nn_;
    const int g = lane >> 2, q4 = lane & 3;
    const int m0 = ks * (Nn_ / KSPLIT);

    const float* fk = g_f + (size_t)ROWS * DIM;
    const float* fv = g_f + 2 * (size_t)ROWS * DIM;

    float acc[9][4];
#pragma unroll
    for (int j = 0; j < 9; j++)
#pragma unroll
        for (int c = 0; c < 4; c++) acc[j][c] = 0.f;

    const int srow = tid >> 4;           // m within chunk (0..15)
    const int dc = (tid & 15) * 4;       // d 0..60 step 4

    // prologue
    {
        int m = m0 + srow;
        const float* vp = fv + (size_t)(b*Nn_ + m)*DIM + h*DH + dc;
        const float* kp = fk + (size_t)(b*Nn_ + m)*DIM + h*DH + dc;
        float ki = g_kinv[base + m];
        float4 vv = *(const float4*)vp;
        float4 kk = *(const float4*)kp;
        float* ar = &As[0][srow][2*dc];
        ar[0] = vv.x; ar[1] = t32f(ki*vv.x);
        ar[2] = vv.y; ar[3] = t32f(ki*vv.y);
        ar[4] = vv.z; ar[5] = t32f(ki*vv.z);
        ar[6] = vv.w; ar[7] = t32f(ki*vv.w);
        *(float4*)&Bs[0][srow][dc] = kk;
        if (tid < 128) {
            int r = tid >> 3, s = tid & 7;
            int mm = m0 + r;
            float v = 0.f;
            if (s == 0) v = t32f(g_kvar [base + mm]);
            else if (s == 1) v = t32f(g_kmean[base + mm]);
            Bs[0][r][64 + s] = v;
        }
    }

    int buf = 0;
    const int KC = Nn_ / KSPLIT;   // 256
    for (int k0 = 16; k0 <= KC; k0 += 16) {
        __syncthreads();
        const bool more = (k0 < KC);
        float4 vv, kk; float ki = 0.f, xv = 0.f;
        if (more) {
            int m = m0 + k0 + srow;
            vv = *(const float4*)(fv + (size_t)(b*Nn_ + m)*DIM + h*DH + dc);
            kk = *(const float4*)(fk + (size_t)(b*Nn_ + m)*DIM + h*DH + dc);
            ki = g_kinv[base + m];
            if (tid < 128) {
                int r = tid >> 3, s = tid & 7;
                int mm = m0 + k0 + r;
                if (s == 0) xv = t32f(g_kvar [base + mm]);
                else if (s == 1) xv = t32f(g_kmean[base + mm]);
            }
        }
#pragma unroll
        for (int ks8 = 0; ks8 < 16; ks8 += 8) {
            unsigned af[4];
            const int mr = warp * 16 + g;
            af[0] = __float_as_uint(As[buf][ks8 + q4][mr]);
            af[1] = __float_as_uint(As[buf][ks8 + q4][mr + 8]);
            af[2] = __float_as_uint(As[buf][ks8 + 4 + q4][mr]);
            af[3] = __float_as_uint(As[buf][ks8 + 4 + q4][mr + 8]);
#pragma unroll
            for (int nt = 0; nt < 9; nt++) {
                unsigned bf[2];
                bf[0] = __float_as_uint(Bs[buf][ks8 + q4][nt * 8 + g]);
                bf[1] = __float_as_uint(Bs[buf][ks8 + 4 + q4][nt * 8 + g]);
                mma8(acc[nt], af, bf);
            }
        }
        if (more) {
            int nb = buf ^ 1;
            float* ar = &As[nb][srow][2*dc];
            ar[0] = vv.x; ar[1] = t32f(ki*vv.x);
            ar[2] = vv.y; ar[3] = t32f(ki*vv.y);
            ar[4] = vv.z; ar[5] = t32f(ki*vv.z);
            ar[6] = vv.w; ar[7] = t32f(ki*vv.w);
            *(float4*)&Bs[nb][srow][dc] = kk;
            if (tid < 128) {
                int r = tid >> 3, s = tid & 7;
                Bs[nb][r][64 + s] = xv;
            }
        }
        buf ^= 1;
    }

    const int row0 = warp * 16 + g;
#pragma unroll
    for (int nt = 0; nt < 9; nt++) {
        const int col = nt * 8 + 2 * q4;
        *(float2*)&g_Mp[ks][hb][row0][col]     = make_float2(acc[nt][0], acc[nt][1]);
        *(float2*)&g_Mp[ks][hb][row0 + 8][col] = make_float2(acc[nt][2], acc[nt][3]);
    }
}

// ---------------- reduce split-K partials ----------------
__global__ void mreduce_kernel()
{
    const int i = blockIdx.x * 256 + threadIdx.x;   // float4 index
    const float4* p0 = (const float4*)&g_Mp[0][0][0][0];
    const float4* p1 = (const float4*)&g_Mp[1][0][0][0];
    const float4* p2 = (const float4*)&g_Mp[2][0][0][0];
    const float4* p3 = (const float4*)&g_Mp[3][0][0][0];
    float4 a = p0[i], b = p1[i], c = p2[i], d = p3[i];
    float4 r = make_float4(a.x+b.x+c.x+d.x, a.y+b.y+c.y+d.y,
                           a.z+b.z+c.z+d.z, a.w+b.w+c.w+d.w);
    ((float4*)&g_Mr[0][0][0])[i] = r;
}

// ================ pgemm: O = combine(fq @ Mcat^T) per hb ================
// C[n, col] = sum_e fq[n,e] * Mr[col][e]; col=2d -> P2, col=2d+1 -> P1
__global__ void __launch_bounds__(256) pgemm_kernel()
{
    __shared__ float As[2][16][136];   // fq [e-chunk][q-row]
    __shared__ float Bs[2][16][136];   // Mr [e-chunk][d' col]
    const int tid = threadIdx.x;
    const int lane = tid & 31, warp = tid >> 5;
    const int wm = (warp >> 2) * 64, wn = (warp & 3) * 32;
    const int hb = blockIdx.y, h = hb >> 2, b = hb & 3;
    const int q0 = blockIdx.x * 128;
    const int base = hb * Nn_;
    const int g = lane >> 2, q4 = lane & 3;

    const float* fq = g_f;

    float acc[4][4][4];
#pragma unroll
    for (int i = 0; i < 4; i++)
#pragma unroll
        for (int j = 0; j < 4; j++)
#pragma unroll
            for (int c = 0; c < 4; c++) acc[i][j][c] = 0.f;

    const int srow = tid >> 1, skc = (tid & 1) * 8;
    const float* Apt = fq + (size_t)(b * Nn_ + q0 + srow) * DIM + h * DH + skc;
    const float* Wpt = &g_Mr[hb][srow][skc];

    {
        float4 a0 = *(const float4*)(Apt);
        float4 a1 = *(const float4*)(Apt + 4);
        float4 w0 = *(const float4*)(Wpt);
        float4 w1 = *(const float4*)(Wpt + 4);
        As[0][skc+0][srow] = a0.x; As[0][skc+1][srow] = a0.y;
        As[0][skc+2][srow] = a0.z; As[0][skc+3][srow] = a0.w;
        As[0][skc+4][srow] = a1.x; As[0][skc+5][srow] = a1.y;
        As[0][skc+6][srow] = a1.z; As[0][skc+7][srow] = a1.w;
        Bs[0][skc+0][srow] = t32f(w0.x); Bs[0][skc+1][srow] = t32f(w0.y);
        Bs[0][skc+2][srow] = t32f(w0.z); Bs[0][skc+3][srow] = t32f(w0.w);
        Bs[0][skc+4][srow] = t32f(w1.x); Bs[0][skc+5][srow] = t32f(w1.y);
        Bs[0][skc+6][srow] = t32f(w1.z); Bs[0][skc+7][srow] = t32f(w1.w);
    }

    int buf = 0;
    for (int k0 = 16; k0 <= DH; k0 += 16) {
        __syncthreads();
        const bool more = (k0 < DH);
        float4 a0, a1, w0, w1;
        if (more) {
            a0 = *(const float4*)(Apt + k0);
            a1 = *(const float4*)(Apt + k0 + 4);
            w0 = *(const float4*)(Wpt + k0);
            w1 = *(const float4*)(Wpt + k0 + 4);
        }
#pragma unroll
        for (int ks = 0; ks < 16; ks += 8) {
            unsigned af[4][4], bf[4][2];
#pragma unroll
            for (int mt = 0; mt < 4; mt++) {
                int mr = wm + mt * 16 + g;
                af[mt][0] = __float_as_uint(As[buf][ks + q4][mr]);
                af[mt][1] = __float_as_uint(As[buf][ks + q4][mr + 8]);
                af[mt][2] = __float_as_uint(As[buf][ks + 4 + q4][mr]);
                af[mt][3] = __float_as_uint(As[buf][ks + 4 + q4][mr + 8]);
            }
#pragma unroll
            for (int nt = 0; nt < 4; nt++) {
                int nc = wn + nt * 8 + g;
                bf[nt][0] = __float_as_uint(Bs[buf][ks + q4][nc]);
                bf[nt][1] = __float_as_uint(Bs[buf][ks + 4 + q4][nc]);
            }
#pragma unroll
            for (int mt = 0; mt < 4; mt++)
#pragma unroll
                for (int nt = 0; nt < 4; nt++)
                    mma8(acc[mt][nt], af[mt], bf[nt]);
        }
        if (more) {
            int nb = buf ^ 1;
            As[nb][skc+0][srow] = a0.x; As[nb][skc+1][srow] = a0.y;
            As[nb][skc+2][srow] = a0.z; As[nb][skc+3][srow] = a0.w;
            As[nb][skc+4][srow] = a1.x; As[nb][skc+5][srow] = a1.y;
            As[nb][skc+6][srow] = a1.z; As[nb][skc+7][srow] = a1.w;
            Bs[nb][skc+0][srow] = t32f(w0.x); Bs[nb][skc+1][srow] = t32f(w0.y);
            Bs[nb][skc+2][srow] = t32f(w0.z); Bs[nb][skc+3][srow] = t32f(w0.w);
            Bs[nb][skc+4][srow] = t32f(w1.x); Bs[nb][skc+5][srow] = t32f(w1.y);
            Bs[nb][skc+6][srow] = t32f(w1.z); Bs[nb][skc+7][srow] = t32f(w1.w);
        }
        buf ^= 1;
    }

    const float cw = g_w3[h * 3 + 0], covw = g_w3[h * 3 + 1], vw = g_w3[h * 3 + 2];
#pragma unroll
    for (int mt = 0; mt < 4; mt++) {
        const int row0 = q0 + wm + mt * 16 + g;
        const float qi0 = g_qinv[base + row0],     qm0 = g_qmean[base + row0],     qv0 = g_qvar[base + row0];
        const float qi1 = g_qinv[base + row0 + 8], qm1 = g_qmean[base + row0 + 8], qv1 = g_qvar[base + row0 + 8];
#pragma unroll
        for (int nt = 0; nt < 4; nt++) {
            const int col = wn + nt * 8 + 2 * q4;   // even
            const int d = col >> 1;
            const float Skv = g_Mr[hb][col][64];
            const float Skm = g_Mr[hb][col][65];
            // c0 = P2(row0,d), c1 = P1(row0,d), c2/c3 same for row0+8
            float o0 = cw * qi0 * acc[mt][nt][1] + (covw / DH) * acc[mt][nt][0]
                     + (vw / DH) * qv0 * Skv - covw * qm0 * Skm;
            float o1 = cw * qi1 * acc[mt][nt][3] + (covw / DH) * acc[mt][nt][2]
                     + (vw / DH) * qv1 * Skv - covw * qm1 * Skm;
            g_ao[(size_t)(b * Nn_ + row0) * DIM + h * DH + d]     = o0;
            g_ao[(size_t)(b * Nn_ + row0 + 8) * DIM + h * DH + d] = o1;
        }
    }
}

// ---------------- per-row stats for fq, fk ----------------
__global__ void stats_kernel(const float* __restrict__ f)
{
    int w = blockIdx.x * 8 + (threadIdx.x >> 5);
    int lane = threadIdx.x & 31;
    int which = w >> 15;
    int rem = w & 32767;
    int n = rem & 1023;
    int b = (rem >> 10) & 3;
    int h = rem >> 12;
    const float* src = f + (size_t)which * ROWS * DIM
                         + ((size_t)(b * Nn_ + n)) * DIM + h * DH;
    float x0 = src[lane], x1 = src[lane + 32];
    float s = x0 + x1, ss = x0 * x0 + x1 * x1;
#pragma unroll
    for (int off = 16; off; off >>= 1) {
        s  += __shfl_xor_sync(0xffffffffu, s, off);
        ss += __shfl_xor_sync(0xffffffffu, ss, off);
    }
    if (lane == 0) {
        int idx = (h * Bq + b) * Nn_ + n;
        float mean = s * (1.f / DH);
        float var  = (ss - s * s * (1.f / DH)) * (1.f / (DH - 1));
        float inv  = rsqrtf(ss);
        if (which == 0) { g_qinv[idx] = inv; g_qmean[idx] = mean; g_qvar[idx] = var; }
        else            { g_kinv[idx] = inv; g_kmean[idx] = mean; g_kvar[idx] = var; }
    }
}

// ---------------- per-head global means ----------------
__global__ void headmean_kernel(const float* __restrict__ f)
{
    int id = blockIdx.x;
    int which = id >> 9;
    int hd = id & 511;
    const float* src = f + (size_t)which * ROWS * DIM + hd;
    float s = 0.f;
    for (int r = threadIdx.x; r < ROWS; r += 256) s += src[(size_t)r * DIM];
    __shared__ float rs[256];
    rs[threadIdx.x] = s;
    __syncthreads();
    for (int off = 128; off > 0; off >>= 1) {
        if (threadIdx.x < off) rs[threadIdx.x] += rs[threadIdx.x + off];
        __syncthreads();
    }
    if (threadIdx.x == 0) g_hg[id] = rs[0] * (1.f / ROWS);
}

// ---------------- gating MLP ----------------
__global__ void mlp_kernel(const float* __restrict__ W1, const float* __restrict__ b1,
                           const float* __restrict__ gg, const float* __restrict__ gb,
                           const float* __restrict__ W2, const float* __restrict__ b2)
{
    int h = threadIdx.x >> 5;
    int lane = threadIdx.x & 31;
    float h1[2];
#pragma unroll
    for (int t = 0; t < 2; t++) {
        int j = lane + t * 32;
        const float* wr = W1 + j * 128;
        float acc = b1[j];
        for (int i = 0; i < 64; i++) acc += g_hg[h * 64 + i] * wr[i];
        for (int i = 0; i < 64; i++) acc += g_hg[512 + h * 64 + i] * wr[64 + i];
        h1[t] = acc;
    }
    float s = h1[0] + h1[1], ss = h1[0] * h1[0] + h1[1] * h1[1];
#pragma unroll
    for (int off = 16; off; off >>= 1) {
        s  += __shfl_xor_sync(0xffffffffu, s, off);
        ss += __shfl_xor_sync(0xffffffffu, ss, off);
    }
    float mean = s * (1.f / 64.f);
    float var  = ss * (1.f / 64.f) - mean * mean;
    float inv  = rsqrtf(var + EPS);
    float hh[2];
#pragma unroll
    for (int t = 0; t < 2; t++) {
        int j = lane + t * 32;
        float v = (h1[t] - mean) * inv * gg[j] + gb[j];
        hh[t] = fmaxf(v, 0.f);
    }
    float lg[3];
#pragma unroll
    for (int c = 0; c < 3; c++) {
        float acc = hh[0] * W2[c * 64 + lane] + hh[1] * W2[c * 64 + lane + 32];
#pragma unroll
        for (int off = 16; off; off >>= 1) acc += __shfl_xor_sync(0xffffffffu, acc, off);
        lg[c] = acc + b2[c];
    }
    if (lane == 0) {
        float m = fmaxf(lg[0], fmaxf(lg[1], lg[2]));
        float e0 = expf(lg[0] - m), e1 = expf(lg[1] - m), e2 = expf(lg[2] - m);
        float inv_s = 1.f / (e0 + e1 + e2);
        g_w3[h * 3 + 0] = e0 * inv_s;
        g_w3[h * 3 + 1] = e1 * inv_s;
        g_w3[h * 3 + 2] = e2 * inv_s;
    }
}

// ---------------- launch ----------------
extern "C" void kernel_launch(void* const* d_in, const int* in_sizes, int n_in,
                              void* d_out, int out_size)
{
    const float* q    = (const float*)d_in[0];
    const float* k    = (const float*)d_in[1];
    const float* v    = (const float*)d_in[2];
    const float* Win  = (const float*)d_in[3];
    const float* Wout = (const float*)d_in[4];
    const float* bout = (const float*)d_in[5];
    const float* g1   = (const float*)d_in[6];
    const float* b1n  = (const float*)d_in[7];
    const float* g2   = (const float*)d_in[8];
    const float* b2n  = (const float*)d_in[9];
    const float* Wup  = (const float*)d_in[10];
    const float* bup  = (const float*)d_in[11];
    const float* Wdn  = (const float*)d_in[12];
    const float* bdn  = (const float*)d_in[13];
    const float* wpW1 = (const float*)d_in[14];
    const float* wpb1 = (const float*)d_in[15];
    const float* wpg  = (const float*)d_in[16];
    const float* wpb  = (const float*)d_in[17];
    const float* wpW2 = (const float*)d_in[18];
    const float* wpb2 = (const float*)d_in[19];
    float* out = (float*)d_out;

    float* xn;  cudaGetSymbolAddress((void**)&xn,  g_xn);
    float* f;   cudaGetSymbolAddress((void**)&f,   g_f);
    float* ao;  cudaGetSymbolAddress((void**)&ao,  g_ao);
    float* q2;  cudaGetSymbolAddress((void**)&q2,  g_q2);
    float* xn2; cudaGetSymbolAddress((void**)&xn2, g_xn2);
    float* u;   cudaGetSymbolAddress((void**)&u,   g_u);

    // 1. LN of q,k,v
    ln_kernel<<<ROWS, 256>>>(q, g1, b1n, xn);
    ln_kernel<<<ROWS, 256>>>(k, g1, b1n, xn + (size_t)ROWS * DIM);
    ln_kernel<<<ROWS, 256>>>(v, g1, b1n, xn + 2 * (size_t)ROWS * DIM);

    // 2. fused projection (output rounded to tf32)
    tmm_kernel<4><<<dim3(DIM / 128, 3 * ROWS / 128), 256>>>(xn, Win, nullptr, nullptr, f,
                                                            3 * ROWS, DIM, DIM);

    // 3. per-row stats + head means + gating MLP
    stats_kernel<<<(2 * HB * Nn_) / 8, 256>>>(f);
    headmean_kernel<<<2 * Hh * DH, 256>>>(f);
    mlp_kernel<<<1, 256>>>(wpW1, wpb1, wpg, wpb, wpW2, wpb2);

    // 4. attention via linear collapse: Mcat build -> reduce -> fq @ Mcat
    mbuild_kernel<<<dim3(KSPLIT, HB), 256>>>();
    mreduce_kernel<<<(HB * 128 * MST) / (4 * 256), 256>>>();
    pgemm_kernel<<<dim3(Nn_ / 128, HB), 256>>>();

    // 5. attn out proj + residual -> q2
    tmm_kernel<3><<<dim3(DIM / 128, ROWS / 128), 256>>>(ao, Wout, bout, q, q2,
                                                        ROWS, DIM, DIM);

    // 6. LN2
    ln_kernel<<<ROWS, 256>>>(q2, g2, b2n, xn2);

    // 7. MLP up + gelu
    tmm_kernel<2><<<dim3(MLPD / 128, ROWS / 128), 256>>>(xn2, Wup, bup, nullptr, u,
                                                         ROWS, MLPD, DIM);

    // 8. MLP down + residual -> out
    tmm_kernel<3><<<dim3(DIM / 128, ROWS / 128), 256>>>(u, Wdn, bdn, q2, out,
                                                        ROWS, DIM, MLPD);
}

// round 7
// speedup vs baseline: 3.7100x; 1.0230x over previous
#include <cuda_runtime.h>
#include <cuda_bf16.h>
#include <math.h>
#include <stdint.h>

// ---------------- problem constants ----------------
#define Bq   4
#define Nn_  1024
#define DIM  512
#define Hh   8
#define DH   64
#define MLPD 2048
#define ROWS (Bq * Nn_)            // 4096 token rows
#define HB   (Hh * Bq)             // 32 attention batches
#define EPS  1e-5f
#define MST  80
#define KSPLIT 4

// ---------------- tf32 mma helpers ----------------
__device__ __forceinline__ float t32f(float x){
    unsigned r; asm("cvt.rna.tf32.f32 %0,%1;" : "=r"(r) : "f"(x));
    return __uint_as_float(r);
}
__device__ __forceinline__ void mma8(float* c, const unsigned* a, const unsigned* b){
    asm("mma.sync.aligned.m16n8k8.row.col.f32.tf32.tf32.f32 "
        "{%0,%1,%2,%3},{%4,%5,%6,%7},{%8,%9},{%0,%1,%2,%3};"
        : "+f"(c[0]), "+f"(c[1]), "+f"(c[2]), "+f"(c[3])
        : "r"(a[0]), "r"(a[1]), "r"(a[2]), "r"(a[3]), "r"(b[0]), "r"(b[1]));
}

// ---------------- device scratch (no allocs allowed) ----------------
__device__ float g_xn [3 * ROWS * DIM];
__device__ float g_f  [3 * ROWS * DIM];
__device__ float g_ao [ROWS * DIM];
__device__ float g_q2 [ROWS * DIM];
__device__ float g_xn2[ROWS * DIM];
__device__ float g_u  [ROWS * MLPD];
__device__ float g_Mp [KSPLIT][HB][128][MST];
__device__ float g_Mr [HB][128][MST];
__device__ float g_qinv [HB * Nn_];
__device__ float g_qmean[HB * Nn_];
__device__ float g_qvar [HB * Nn_];
__device__ float g_kinv [HB * Nn_];
__device__ float g_kmean[HB * Nn_];
__device__ float g_kvar [HB * Nn_];
__device__ float g_hg [2 * Hh * DH];
__device__ float g_w3 [Hh * 3];

// ---------------- fused layernorm of q,k,v ----------------
__global__ void ln3_kernel(const float* __restrict__ q, const float* __restrict__ k,
                           const float* __restrict__ v, const float* __restrict__ g,
                           const float* __restrict__ bb, float* __restrict__ y)
{
    int row = blockIdx.x;                 // 0 .. 3*ROWS-1
    int which = row >> 12;
    const float* x = (which == 0) ? q : (which == 1) ? k : v;
    int tid = threadIdx.x;
    const float* xr = x + (size_t)(row & (ROWS - 1)) * DIM;
    float v0 = xr[tid], v1 = xr[tid + 256];
    float s = v0 + v1, ss = v0 * v0 + v1 * v1;
    __shared__ float rs[256], rss[256];
    rs[tid] = s; rss[tid] = ss;
    __syncthreads();
    for (int off = 128; off > 0; off >>= 1) {
        if (tid < off) { rs[tid] += rs[tid + off]; rss[tid] += rss[tid + off]; }
        __syncthreads();
    }
    float mean = rs[0] * (1.f / DIM);
    float var  = rss[0] * (1.f / DIM) - mean * mean;
    float inv  = rsqrtf(var + EPS);
    float* yr = y + (size_t)row * DIM;
    yr[tid]       = (v0 - mean) * inv * g[tid]       + bb[tid];
    yr[tid + 256] = (v1 - mean) * inv * g[tid + 256] + bb[tid + 256];
}

// ---------------- layernorm (single tensor, for LN2) ----------------
__global__ void ln_kernel(const float* __restrict__ x, const float* __restrict__ g,
                          const float* __restrict__ bb, float* __restrict__ y)
{
    int row = blockIdx.x;
    int tid = threadIdx.x;
    const float* xr = x + (size_t)row * DIM;
    float v0 = xr[tid], v1 = xr[tid + 256];
    float s = v0 + v1, ss = v0 * v0 + v1 * v1;
    __shared__ float rs[256], rss[256];
    rs[tid] = s; rss[tid] = ss;
    __syncthreads();
    for (int off = 128; off > 0; off >>= 1) {
        if (tid < off) { rs[tid] += rs[tid + off]; rss[tid] += rss[tid + off]; }
        __syncthreads();
    }
    float mean = rs[0] * (1.f / DIM);
    float var  = rss[0] * (1.f / DIM) - mean * mean;
    float inv  = rsqrtf(var + EPS);
    float* yr = y + (size_t)row * DIM;
    yr[tid]       = (v0 - mean) * inv * g[tid]       + bb[tid];
    yr[tid + 256] = (v1 - mean) * inv * g[tid + 256] + bb[tid + 256];
}

// ================ tf32 mma GEMM, fragment-layout smem ================
// C = A[M,K] @ W[N,K]^T.  CTA tile (MT*32) x 128, BK=16, double-buffered.
// Fragments stored in mma-register order: A -> LDS.128, B -> LDS.64.
// MODE: 2 +bias+gelu, 3 +bias+residual, 4 plain+tf32-round
template <int MODE, int MT>
__global__ void __launch_bounds__(256) tmm2_kernel(
    const float* __restrict__ A, const float* __restrict__ W,
    const float* __restrict__ bias, const float* __restrict__ res,
    float* __restrict__ C, int M, int Nc, int K)
{
    __shared__ __align__(16) float Af[2][MT * 2 * 2 * 128];  // [(mtile*2+kc)*128 + lane*4 + reg]
    __shared__ __align__(16) float Bf[2][16 * 2 * 64];       // [(ntile*2+kc)*64 + lane*2 + reg]
    const int tid = threadIdx.x;
    const int lane = tid & 31, warp = tid >> 5;
    const int wm = (warp >> 2) * (MT * 16);
    const int wn = (warp & 3) * 32;
    const int m0 = blockIdx.y * (MT * 32), n0 = blockIdx.x * 128;
    const int g = lane >> 2, q4 = lane & 3;

    float acc[MT][4][4];
#pragma unroll
    for (int i = 0; i < MT; i++)
#pragma unroll
        for (int j = 0; j < 4; j++)
#pragma unroll
            for (int c = 0; c < 4; c++) acc[i][j][c] = 0.f;

    // ---- staging thread mappings ----
    // B side (all MT): 128 rows, 2 threads/row
    const int bsrow = tid >> 1, bkc = tid & 1;
    const float* Wp = W + (size_t)(n0 + bsrow) * K + bkc * 8;
    const int bnt = bsrow >> 3, bg = bsrow & 7;
    // A side
    const int asrow = (MT == 4) ? (tid >> 1) : (tid >> 2);
    const int akoff = (MT == 4) ? ((tid & 1) * 8) : ((tid & 3) * 4);
    const float* Ap = A + (size_t)(m0 + asrow) * K + akoff;
    const int amt = asrow >> 4, arl = asrow & 15, ag = arl & 7, arb = arl >> 3;
    const int akc = akoff >> 3;
    const int akh = (akoff & 7) >> 2;   // used for MT==2 only

    float4 av0, av1, wv0, wv1;

    // ---- prologue: load+store chunk 0 into buf 0 ----
    av0 = *(const float4*)(Ap);
    if (MT == 4) av1 = *(const float4*)(Ap + 4);
    wv0 = *(const float4*)(Wp);
    wv1 = *(const float4*)(Wp + 4);
    {
        float* ab = &Af[0][(amt * 2 + akc) * 128];
        if (MT == 4) {
            float va[8] = {av0.x, av0.y, av0.z, av0.w, av1.x, av1.y, av1.z, av1.w};
#pragma unroll
            for (int t = 0; t < 8; t++) {
                int kk = (t + ag) & 7;
                ab[(ag * 4 + (kk & 3)) * 4 + arb + 2 * (kk >> 2)] = t32f(va[kk]);
            }
        } else {
            float va[4] = {av0.x, av0.y, av0.z, av0.w};
#pragma unroll
            for (int t = 0; t < 4; t++) {
                int qq = (t + ag) & 3;
                ab[(ag * 4 + qq) * 4 + arb + 2 * akh] = t32f(va[qq]);
            }
        }
        float* bb2 = &Bf[0][(bnt * 2 + bkc) * 64 + bg * 8];
        *(float4*)&bb2[0] = make_float4(t32f(wv0.x), t32f(wv1.x), t32f(wv0.y), t32f(wv1.y));
        *(float4*)&bb2[4] = make_float4(t32f(wv0.z), t32f(wv1.z), t32f(wv0.w), t32f(wv1.w));
    }

    int buf = 0;
    for (int k0 = 16; k0 <= K; k0 += 16) {
        __syncthreads();
        const bool more = (k0 < K);
        if (more) {
            av0 = *(const float4*)(Ap + k0);
            if (MT == 4) av1 = *(const float4*)(Ap + k0 + 4);
            wv0 = *(const float4*)(Wp + k0);
            wv1 = *(const float4*)(Wp + k0 + 4);
        }
        // ---- compute on buf ----
#pragma unroll
        for (int kc = 0; kc < 2; kc++) {
            float4 afv[MT]; float2 bfv[4];
#pragma unroll
            for (int mt = 0; mt < MT; mt++)
                afv[mt] = *(const float4*)&Af[buf][((((wm >> 4) + mt) * 2 + kc) * 128) + lane * 4];
#pragma unroll
            for (int nt = 0; nt < 4; nt++)
                bfv[nt] = *(const float2*)&Bf[buf][((((wn >> 3) + nt) * 2 + kc) * 64) + lane * 2];
#pragma unroll
            for (int mt = 0; mt < MT; mt++)
#pragma unroll
                for (int nt = 0; nt < 4; nt++)
                    mma8(acc[mt][nt], (const unsigned*)&afv[mt], (const unsigned*)&bfv[nt]);
        }
        if (more) {
            const int nb = buf ^ 1;
            float* ab = &Af[nb][(amt * 2 + akc) * 128];
            if (MT == 4) {
                float va[8] = {av0.x, av0.y, av0.z, av0.w, av1.x, av1.y, av1.z, av1.w};
#pragma unroll
                for (int t = 0; t < 8; t++) {
                    int kk = (t + ag) & 7;
                    ab[(ag * 4 + (kk & 3)) * 4 + arb + 2 * (kk >> 2)] = t32f(va[kk]);
                }
            } else {
                float va[4] = {av0.x, av0.y, av0.z, av0.w};
#pragma unroll
                for (int t = 0; t < 4; t++) {
                    int qq = (t + ag) & 3;
                    ab[(ag * 4 + qq) * 4 + arb + 2 * akh] = t32f(va[qq]);
                }
            }
            float* bb2 = &Bf[nb][(bnt * 2 + bkc) * 64 + bg * 8];
            *(float4*)&bb2[0] = make_float4(t32f(wv0.x), t32f(wv1.x), t32f(wv0.y), t32f(wv1.y));
            *(float4*)&bb2[4] = make_float4(t32f(wv0.z), t32f(wv1.z), t32f(wv0.w), t32f(wv1.w));
        }
        buf ^= 1;
    }

    // ---- epilogue ----
#pragma unroll
    for (int mt = 0; mt < MT; mt++) {
        const int row0 = m0 + wm + mt * 16 + g;
#pragma unroll
        for (int nt = 0; nt < 4; nt++) {
            const int col = n0 + wn + nt * 8 + 2 * q4;
            float v0 = acc[mt][nt][0], v1 = acc[mt][nt][1];
            float v2 = acc[mt][nt][2], v3 = acc[mt][nt][3];
            if (MODE == 2 || MODE == 3) {
                float2 bv = *(const float2*)&bias[col];
                v0 += bv.x; v1 += bv.y; v2 += bv.x; v3 += bv.y;
            }
            if (MODE == 2) {
                v0 = 0.5f * v0 * (1.f + erff(v0 * 0.70710678118654752f));
                v1 = 0.5f * v1 * (1.f + erff(v1 * 0.70710678118654752f));
                v2 = 0.5f * v2 * (1.f + erff(v2 * 0.70710678118654752f));
                v3 = 0.5f * v3 * (1.f + erff(v3 * 0.70710678118654752f));
            }
            if (MODE == 3) {
                float2 r0 = *(const float2*)(res + (size_t)row0 * Nc + col);
                float2 r1 = *(const float2*)(res + (size_t)(row0 + 8) * Nc + col);
                v0 += r0.x; v1 += r0.y; v2 += r1.x; v3 += r1.y;
            }
            if (MODE == 4) {
                v0 = t32f(v0); v1 = t32f(v1); v2 = t32f(v2); v3 = t32f(v3);
            }
            *(float2*)(C + (size_t)row0 * Nc + col)       = make_float2(v0, v1);
            *(float2*)(C + (size_t)(row0 + 8) * Nc + col) = make_float2(v2, v3);
        }
    }
}

// ================ mbuild: Mcat[d'=128][e=72] = Vx^T @ Ax per hb (split-K) ======
__global__ void __launch_bounds__(256) mbuild_kernel()
{
    __shared__ float As[2][16][136];
    __shared__ float Bs[2][16][72];
    const int tid = threadIdx.x, lane = tid & 31, warp = tid >> 5;
    const int ks = blockIdx.x, hb = blockIdx.y, h = hb >> 2, b = hb & 3;
    const int base = hb * Nn_;
    const int g = lane >> 2, q4 = lane & 3;
    const int m0 = ks * (Nn_ / KSPLIT);

    const float* fk = g_f + (size_t)ROWS * DIM;
    const float* fv = g_f + 2 * (size_t)ROWS * DIM;

    float acc[9][4];
#pragma unroll
    for (int j = 0; j < 9; j++)
#pragma unroll
        for (int c = 0; c < 4; c++) acc[j][c] = 0.f;

    const int srow = tid >> 4;
    const int dc = (tid & 15) * 4;

    {
        int m = m0 + srow;
        float ki = g_kinv[base + m];
        float4 vv = *(const float4*)(fv + (size_t)(b*Nn_ + m)*DIM + h*DH + dc);
        float4 kk = *(const float4*)(fk + (size_t)(b*Nn_ + m)*DIM + h*DH + dc);
        float* ar = &As[0][srow][2*dc];
        ar[0] = vv.x; ar[1] = t32f(ki*vv.x);
        ar[2] = vv.y; ar[3] = t32f(ki*vv.y);
        ar[4] = vv.z; ar[5] = t32f(ki*vv.z);
        ar[6] = vv.w; ar[7] = t32f(ki*vv.w);
        *(float4*)&Bs[0][srow][dc] = kk;
        if (tid < 128) {
            int r = tid >> 3, s = tid & 7;
            int mm = m0 + r;
            float v = 0.f;
            if (s == 0) v = t32f(g_kvar [base + mm]);
            else if (s == 1) v = t32f(g_kmean[base + mm]);
            Bs[0][r][64 + s] = v;
        }
    }

    int buf = 0;
    const int KC = Nn_ / KSPLIT;
    for (int k0 = 16; k0 <= KC; k0 += 16) {
        __syncthreads();
        const bool more = (k0 < KC);
        float4 vv, kk; float ki = 0.f, xv = 0.f;
        if (more) {
            int m = m0 + k0 + srow;
            vv = *(const float4*)(fv + (size_t)(b*Nn_ + m)*DIM + h*DH + dc);
            kk = *(const float4*)(fk + (size_t)(b*Nn_ + m)*DIM + h*DH + dc);
            ki = g_kinv[base + m];
            if (tid < 128) {
                int r = tid >> 3, s = tid & 7;
                int mm = m0 + k0 + r;
                if (s == 0) xv = t32f(g_kvar [base + mm]);
                else if (s == 1) xv = t32f(g_kmean[base + mm]);
            }
        }
#pragma unroll
        for (int ks8 = 0; ks8 < 16; ks8 += 8) {
            unsigned af[4];
            const int mr = warp * 16 + g;
            af[0] = __float_as_uint(As[buf][ks8 + q4][mr]);
            af[1] = __float_as_uint(As[buf][ks8 + q4][mr + 8]);
            af[2] = __float_as_uint(As[buf][ks8 + 4 + q4][mr]);
            af[3] = __float_as_uint(As[buf][ks8 + 4 + q4][mr + 8]);
#pragma unroll
            for (int nt = 0; nt < 9; nt++) {
                unsigned bf[2];
                bf[0] = __float_as_uint(Bs[buf][ks8 + q4][nt * 8 + g]);
                bf[1] = __float_as_uint(Bs[buf][ks8 + 4 + q4][nt * 8 + g]);
                mma8(acc[nt], af, bf);
            }
        }
        if (more) {
            int nb = buf ^ 1;
            float* ar = &As[nb][srow][2*dc];
            ar[0] = vv.x; ar[1] = t32f(ki*vv.x);
            ar[2] = vv.y; ar[3] = t32f(ki*vv.y);
            ar[4] = vv.z; ar[5] = t32f(ki*vv.z);
            ar[6] = vv.w; ar[7] = t32f(ki*vv.w);
            *(float4*)&Bs[nb][srow][dc] = kk;
            if (tid < 128) {
                int r = tid >> 3, s = tid & 7;
                Bs[nb][r][64 + s] = xv;
            }
        }
        buf ^= 1;
    }

    const int row0 = warp * 16 + g;
#pragma unroll
    for (int nt = 0; nt < 9; nt++) {
        const int col = nt * 8 + 2 * q4;
        *(float2*)&g_Mp[ks][hb][row0][col]     = make_float2(acc[nt][0], acc[nt][1]);
        *(float2*)&g_Mp[ks][hb][row0 + 8][col] = make_float2(acc[nt][2], acc[nt][3]);
    }
}

// ---------------- reduce split-K partials ----------------
__global__ void mreduce_kernel()
{
    const int i = blockIdx.x * 256 + threadIdx.x;
    const float4* p0 = (const float4*)&g_Mp[0][0][0][0];
    const float4* p1 = (const float4*)&g_Mp[1][0][0][0];
    const float4* p2 = (const float4*)&g_Mp[2][0][0][0];
    const float4* p3 = (const float4*)&g_Mp[3][0][0][0];
    float4 a = p0[i], b = p1[i], c = p2[i], d = p3[i];
    ((float4*)&g_Mr[0][0][0])[i] = make_float4(a.x+b.x+c.x+d.x, a.y+b.y+c.y+d.y,
                                               a.z+b.z+c.z+d.z, a.w+b.w+c.w+d.w);
}

// ================ pgemm: O = combine(fq @ Mcat^T) per hb ================
__global__ void __launch_bounds__(256) pgemm_kernel()
{
    __shared__ float As[2][16][136];
    __shared__ float Bs[2][16][136];
    const int tid = threadIdx.x;
    const int lane = tid & 31, warp = tid >> 5;
    const int wm = (warp >> 2) * 64, wn = (warp & 3) * 32;
    const int hb = blockIdx.y, h = hb >> 2, b = hb & 3;
    const int q0 = blockIdx.x * 128;
    const int base = hb * Nn_;
    const int g = lane >> 2, q4 = lane & 3;

    const float* fq = g_f;

    float acc[4][4][4];
#pragma unroll
    for (int i = 0; i < 4; i++)
#pragma unroll
        for (int j = 0; j < 4; j++)
#pragma unroll
            for (int c = 0; c < 4; c++) acc[i][j][c] = 0.f;

    const int srow = tid >> 1, skc = (tid & 1) * 8;
    const float* Apt = fq + (size_t)(b * Nn_ + q0 + srow) * DIM + h * DH + skc;
    const float* Wpt = &g_Mr[hb][srow][skc];

    {
        float4 a0 = *(const float4*)(Apt);
        float4 a1 = *(const float4*)(Apt + 4);
        float4 w0 = *(const float4*)(Wpt);
        float4 w1 = *(const float4*)(Wpt + 4);
        As[0][skc+0][srow] = a0.x; As[0][skc+1][srow] = a0.y;
        As[0][skc+2][srow] = a0.z; As[0][skc+3][srow] = a0.w;
        As[0][skc+4][srow] = a1.x; As[0][skc+5][srow] = a1.y;
        As[0][skc+6][srow] = a1.z; As[0][skc+7][srow] = a1.w;
        Bs[0][skc+0][srow] = t32f(w0.x); Bs[0][skc+1][srow] = t32f(w0.y);
        Bs[0][skc+2][srow] = t32f(w0.z); Bs[0][skc+3][srow] = t32f(w0.w);
        Bs[0][skc+4][srow] = t32f(w1.x); Bs[0][skc+5][srow] = t32f(w1.y);
        Bs[0][skc+6][srow] = t32f(w1.z); Bs[0][skc+7][srow] = t32f(w1.w);
    }

    int buf = 0;
    for (int k0 = 16; k0 <= DH; k0 += 16) {
        __syncthreads();
        const bool more = (k0 < DH);
        float4 a0, a1, w0, w1;
        if (more) {
            a0 = *(const float4*)(Apt + k0);
            a1 = *(const float4*)(Apt + k0 + 4);
            w0 = *(const float4*)(Wpt + k0);
            w1 = *(const float4*)(Wpt + k0 + 4);
        }
#pragma unroll
        for (int ks = 0; ks < 16; ks += 8) {
            unsigned af[4][4], bf[4][2];
#pragma unroll
            for (int mt = 0; mt < 4; mt++) {
                int mr = wm + mt * 16 + g;
                af[mt][0] = __float_as_uint(As[buf][ks + q4][mr]);
                af[mt][1] = __float_as_uint(As[buf][ks + q4][mr + 8]);
                af[mt][2] = __float_as_uint(As[buf][ks + 4 + q4][mr]);
                af[mt][3] = __float_as_uint(As[buf][ks + 4 + q4][mr + 8]);
            }
#pragma unroll
            for (int nt = 0; nt < 4; nt++) {
                int nc = wn + nt * 8 + g;
                bf[nt][0] = __float_as_uint(Bs[buf][ks + q4][nc]);
                bf[nt][1] = __float_as_uint(Bs[buf][ks + 4 + q4][nc]);
            }
#pragma unroll
            for (int mt = 0; mt < 4; mt++)
#pragma unroll
                for (int nt = 0; nt < 4; nt++)
                    mma8(acc[mt][nt], af[mt], bf[nt]);
        }
        if (more) {
            int nb = buf ^ 1;
            As[nb][skc+0][srow] = a0.x; As[nb][skc+1][srow] = a0.y;
            As[nb][skc+2][srow] = a0.z; As[nb][skc+3][srow] = a0.w;
            As[nb][skc+4][srow] = a1.x; As[nb][skc+5][srow] = a1.y;
            As[nb][skc+6][srow] = a1.z; As[nb][skc+7][srow] = a1.w;
            Bs[nb][skc+0][srow] = t32f(w0.x); Bs[nb][skc+1][srow] = t32f(w0.y);
            Bs[nb][skc+2][srow] = t32f(w0.z); Bs[nb][skc+3][srow] = t32f(w0.w);
            Bs[nb][skc+4][srow] = t32f(w1.x); Bs[nb][skc+5][srow] = t32f(w1.y);
            Bs[nb][skc+6][srow] = t32f(w1.z); Bs[nb][skc+7][srow] = t32f(w1.w);
        }
        buf ^= 1;
    }

    const float cw = g_w3[h * 3 + 0], covw = g_w3[h * 3 + 1], vw = g_w3[h * 3 + 2];
#pragma unroll
    for (int mt = 0; mt < 4; mt++) {
        const int row0 = q0 + wm + mt * 16 + g;
        const float qi0 = g_qinv[base + row0],     qm0 = g_qmean[base + row0],     qv0 = g_qvar[base + row0];
        const float qi1 = g_qinv[base + row0 + 8], qm1 = g_qmean[base + row0 + 8], qv1 = g_qvar[base + row0 + 8];
#pragma unroll
        for (int nt = 0; nt < 4; nt++) {
            const int col = wn + nt * 8 + 2 * q4;
            const int d = col >> 1;
            const float Skv = g_Mr[hb][col][64];
            const float Skm = g_Mr[hb][col][65];
            float o0 = cw * qi0 * acc[mt][nt][1] + (covw / DH) * acc[mt][nt][0]
                     + (vw / DH) * qv0 * Skv - covw * qm0 * Skm;
            float o1 = cw * qi1 * acc[mt][nt][3] + (covw / DH) * acc[mt][nt][2]
                     + (vw / DH) * qv1 * Skv - covw * qm1 * Skm;
            g_ao[(size_t)(b * Nn_ + row0) * DIM + h * DH + d]     = o0;
            g_ao[(size_t)(b * Nn_ + row0 + 8) * DIM + h * DH + d] = o1;
        }
    }
}

// ---------------- per-row stats for fq, fk ----------------
__global__ void stats_kernel(const float* __restrict__ f)
{
    int w = blockIdx.x * 8 + (threadIdx.x >> 5);
    int lane = threadIdx.x & 31;
    int which = w >> 15;
    int rem = w & 32767;
    int n = rem & 1023;
    int b = (rem >> 10) & 3;
    int h = rem >> 12;
    const float* src = f + (size_t)which * ROWS * DIM
                         + ((size_t)(b * Nn_ + n)) * DIM + h * DH;
    float x0 = src[lane], x1 = src[lane + 32];
    float s = x0 + x1, ss = x0 * x0 + x1 * x1;
#pragma unroll
    for (int off = 16; off; off >>= 1) {
        s  += __shfl_xor_sync(0xffffffffu, s, off);
        ss += __shfl_xor_sync(0xffffffffu, ss, off);
    }
    if (lane == 0) {
        int idx = (h * Bq + b) * Nn_ + n;
        float mean = s * (1.f / DH);
        float var  = (ss - s * s * (1.f / DH)) * (1.f / (DH - 1));
        float inv  = rsqrtf(ss);
        if (which == 0) { g_qinv[idx] = inv; g_qmean[idx] = mean; g_qvar[idx] = var; }
        else            { g_kinv[idx] = inv; g_kmean[idx] = mean; g_kvar[idx] = var; }
    }
}

// ---------------- per-head global sums (coalesced) ----------------
__global__ void zero_hg_kernel()
{
    g_hg[blockIdx.x * 256 + threadIdx.x] = 0.f;
}
__global__ void headmean2_kernel(const float* __restrict__ f)
{
    const int which = blockIdx.x >> 4, chunk = blockIdx.x & 15;
    const int col = threadIdx.x;       // 512 threads
    const float* src = f + (size_t)which * ROWS * DIM + (size_t)chunk * 256 * DIM + col;
    float s = 0.f;
    for (int r = 0; r < 256; r++) s += src[(size_t)r * DIM];
    atomicAdd(&g_hg[which * 512 + col], s);
}

// ---------------- gating MLP (g_hg now holds SUMS; scale by 1/ROWS) ----------------
__global__ void mlp_kernel(const float* __restrict__ W1, const float* __restrict__ b1,
                           const float* __restrict__ gg, const float* __restrict__ gb,
                           const float* __restrict__ W2, const float* __restrict__ b2)
{
    int h = threadIdx.x >> 5;
    int lane = threadIdx.x & 31;
    const float invR = 1.f / (float)ROWS;
    float h1[2];
#pragma unroll
    for (int t = 0; t < 2; t++) {
        int j = lane + t * 32;
        const float* wr = W1 + j * 128;
        float dot = 0.f;
        for (int i = 0; i < 64; i++) dot += g_hg[h * 64 + i] * wr[i];
        for (int i = 0; i < 64; i++) dot += g_hg[512 + h * 64 + i] * wr[64 + i];
        h1[t] = b1[j] + dot * invR;
    }
    float s = h1[0] + h1[1], ss = h1[0] * h1[0] + h1[1] * h1[1];
#pragma unroll
    for (int off = 16; off; off >>= 1) {
        s  += __shfl_xor_sync(0xffffffffu, s, off);
        ss += __shfl_xor_sync(0xffffffffu, ss, off);
    }
    float mean = s * (1.f / 64.f);
    float var  = ss * (1.f / 64.f) - mean * mean;
    float inv  = rsqrtf(var + EPS);
    float hh[2];
#pragma unroll
    for (int t = 0; t < 2; t++) {
        int j = lane + t * 32;
        float v = (h1[t] - mean) * inv * gg[j] + gb[j];
        hh[t] = fmaxf(v, 0.f);
    }
    float lg[3];
#pragma unroll
    for (int c = 0; c < 3; c++) {
        float acc = hh[0] * W2[c * 64 + lane] + hh[1] * W2[c * 64 + lane + 32];
#pragma unroll
        for (int off = 16; off; off >>= 1) acc += __shfl_xor_sync(0xffffffffu, acc, off);
        lg[c] = acc + b2[c];
    }
    if (lane == 0) {
        float m = fmaxf(lg[0], fmaxf(lg[1], lg[2]));
        float e0 = expf(lg[0] - m), e1 = expf(lg[1] - m), e2 = expf(lg[2] - m);
        float inv_s = 1.f / (e0 + e1 + e2);
        g_w3[h * 3 + 0] = e0 * inv_s;
        g_w3[h * 3 + 1] = e1 * inv_s;
        g_w3[h * 3 + 2] = e2 * inv_s;
    }
}

// ---------------- launch ----------------
extern "C" void kernel_launch(void* const* d_in, const int* in_sizes, int n_in,
                              void* d_out, int out_size)
{
    const float* q    = (const float*)d_in[0];
    const float* k    = (const float*)d_in[1];
    const float* v    = (const float*)d_in[2];
    const float* Win  = (const float*)d_in[3];
    const float* Wout = (const float*)d_in[4];
    const float* bout = (const float*)d_in[5];
    const float* g1   = (const float*)d_in[6];
    const float* b1n  = (const float*)d_in[7];
    const float* g2   = (const float*)d_in[8];
    const float* b2n  = (const float*)d_in[9];
    const float* Wup  = (const float*)d_in[10];
    const float* bup  = (const float*)d_in[11];
    const float* Wdn  = (const float*)d_in[12];
    const float* bdn  = (const float*)d_in[13];
    const float* wpW1 = (const float*)d_in[14];
    const float* wpb1 = (const float*)d_in[15];
    const float* wpg  = (const float*)d_in[16];
    const float* wpb  = (const float*)d_in[17];
    const float* wpW2 = (const float*)d_in[18];
    const float* wpb2 = (const float*)d_in[19];
    float* out = (float*)d_out;

    float* xn;  cudaGetSymbolAddress((void**)&xn,  g_xn);
    float* f;   cudaGetSymbolAddress((void**)&f,   g_f);
    float* ao;  cudaGetSymbolAddress((void**)&ao,  g_ao);
    float* q2;  cudaGetSymbolAddress((void**)&q2,  g_q2);
    float* xn2; cudaGetSymbolAddress((void**)&xn2, g_xn2);
    float* u;   cudaGetSymbolAddress((void**)&u,   g_u);

    // 1. fused LN of q,k,v (one launch)
    ln3_kernel<<<3 * ROWS, 256>>>(q, k, v, g1, b1n, xn);

    // 2. fused projection (output rounded to tf32)
    tmm2_kernel<4, 4><<<dim3(DIM / 128, 3 * ROWS / 128), 256>>>(
        xn, Win, nullptr, nullptr, f, 3 * ROWS, DIM, DIM);

    // 3. per-row stats + per-head sums + gating MLP
    stats_kernel<<<(2 * HB * Nn_) / 8, 256>>>(f);
    zero_hg_kernel<<<4, 256>>>();
    headmean2_kernel<<<32, 512>>>(f);
    mlp_kernel<<<1, 256>>>(wpW1, wpb1, wpg, wpb, wpW2, wpb2);

    // 4. attention via linear collapse
    mbuild_kernel<<<dim3(KSPLIT, HB), 256>>>();
    mreduce_kernel<<<(HB * 128 * MST) / (4 * 256), 256>>>();
    pgemm_kernel<<<dim3(Nn_ / 128, HB), 256>>>();

    // 5. attn out proj + residual -> q2  (M64 tile: 256 CTAs)
    tmm2_kernel<3, 2><<<dim3(DIM / 128, ROWS / 64), 256>>>(
        ao, Wout, bout, q, q2, ROWS, DIM, DIM);

    // 6. LN2
    ln_kernel<<<ROWS, 256>>>(q2, g2, b2n, xn2);

    // 7. MLP up + gelu
    tmm2_kernel<2, 4><<<dim3(MLPD / 128, ROWS / 128), 256>>>(
        xn2, Wup, bup, nullptr, u, ROWS, MLPD, DIM);

    // 8. MLP down + residual -> out  (M64 tile: 256 CTAs)
    tmm2_kernel<3, 2><<<dim3(DIM / 128, ROWS / 64), 256>>>(
        u, Wdn, bdn, q2, out, ROWS, DIM, MLPD);
}